// round 4
// baseline (speedup 1.0000x reference)
#include <cuda_runtime.h>
#include <math.h>
#include <stdint.h>

#define L_SEQ 2048
#define B_SZ 2
#define E_DIM 256
#define NH 8
#define HD 32
#define M_ROWS (L_SEQ * B_SZ)   // 4096

// Scratch (allocation-free rule: __device__ globals)
static __device__ float g_Q[M_ROWS * E_DIM];
static __device__ float g_K[M_ROWS * E_DIM];
static __device__ float g_V[M_ROWS * E_DIM];
static __device__ float g_O[M_ROWS * E_DIM];

// ---------------------------------------------------------------------------
// helpers: tf32 convert / hi-lo split / mma
// ---------------------------------------------------------------------------
__device__ __forceinline__ uint32_t f2tf(float x) {
    uint32_t r; asm("cvt.rna.tf32.f32 %0, %1;" : "=r"(r) : "f"(x)); return r;
}
__device__ __forceinline__ void split2(float x, float& hi, float& lo) {
    uint32_t h = f2tf(x);
    hi = __uint_as_float(h);
    lo = __uint_as_float(f2tf(x - hi));
}
__device__ __forceinline__ void mma8(float c[4], const uint32_t a[4],
                                     uint32_t b0, uint32_t b1) {
    asm volatile(
        "mma.sync.aligned.m16n8k8.row.col.f32.tf32.tf32.f32 "
        "{%0,%1,%2,%3}, {%4,%5,%6,%7}, {%8,%9}, {%0,%1,%2,%3};"
        : "+f"(c[0]), "+f"(c[1]), "+f"(c[2]), "+f"(c[3])
        : "r"(a[0]), "r"(a[1]), "r"(a[2]), "r"(a[3]), "r"(b0), "r"(b1));
}

// ---------------------------------------------------------------------------
// TF32 GEMM: out[M,N] = X[M,256] @ W[256,N] + bias[N], 3-term split (fp32 acc).
// CTA: 128 threads (4 warps), tile 64(M)x64(N), K-chunk 32.
// Warp w computes rows w*16..w*16+15 x all 64 cols (8 m16n8 tiles).
// Smem: A [m 64][k 32] pitch 36 (hi/lo), B [k 32][n 64] pitch 72 (hi/lo).
// All fragment LDS patterns conflict-free (checked bank maps).
// ---------------------------------------------------------------------------
#define GA_PITCH 36
#define GB_PITCH 72

__global__ __launch_bounds__(128) void gemm_tf32_kernel(
    const float* __restrict__ X, const float* __restrict__ W,
    const float* __restrict__ bias, float* __restrict__ out)
{
    __shared__ float Ahi[64 * GA_PITCH];
    __shared__ float Alo[64 * GA_PITCH];
    __shared__ float Bhi[32 * GB_PITCH];
    __shared__ float Blo[32 * GB_PITCH];

    const int tid  = threadIdx.x;
    const int warp = tid >> 5;
    const int lane = tid & 31;
    const int g    = lane >> 2;
    const int t4   = lane & 3;
    const int mBase = blockIdx.y * 64;
    const int nBase = blockIdx.x * 64;
    const int m0 = warp * 16;

    float c[8][4];
    #pragma unroll
    for (int nt = 0; nt < 8; nt++)
        c[nt][0] = c[nt][1] = c[nt][2] = c[nt][3] = 0.f;

    for (int k0 = 0; k0 < 256; k0 += 32) {
        // ---- load X tile 64x32 (512 float4s, 4 per thread) ----
        #pragma unroll
        for (int it = 0; it < 4; it++) {
            int idx = tid + it * 128;
            int row = idx >> 3;
            int cg  = (idx & 7) << 2;
            float4 a = *(const float4*)&X[(mBase + row) * 256 + k0 + cg];
            float4 hf, lf;
            split2(a.x, hf.x, lf.x); split2(a.y, hf.y, lf.y);
            split2(a.z, hf.z, lf.z); split2(a.w, hf.w, lf.w);
            *(float4*)&Ahi[row * GA_PITCH + cg] = hf;
            *(float4*)&Alo[row * GA_PITCH + cg] = lf;
        }
        // ---- load W tile 32x64 (512 float4s) into [k][n] layout ----
        #pragma unroll
        for (int it = 0; it < 4; it++) {
            int idx = tid + it * 128;
            int r   = idx >> 4;            // k row 0..31
            int ncg = (idx & 15) << 2;     // n col group
            float4 w = *(const float4*)&W[(k0 + r) * 256 + nBase + ncg];
            float4 hf, lf;
            split2(w.x, hf.x, lf.x); split2(w.y, hf.y, lf.y);
            split2(w.z, hf.z, lf.z); split2(w.w, hf.w, lf.w);
            *(float4*)&Bhi[r * GB_PITCH + ncg] = hf;
            *(float4*)&Blo[r * GB_PITCH + ncg] = lf;
        }
        __syncthreads();

        // ---- compute: 4 k8-blocks x 8 n-tiles x 3 mmas ----
        #pragma unroll
        for (int kk = 0; kk < 4; kk++) {
            int ka = kk * 8 + t4;
            int r0 = (m0 + g) * GA_PITCH;
            int r1 = (m0 + g + 8) * GA_PITCH;
            uint32_t ah[4], al[4];
            ah[0] = __float_as_uint(Ahi[r0 + ka]);
            ah[1] = __float_as_uint(Ahi[r1 + ka]);
            ah[2] = __float_as_uint(Ahi[r0 + ka + 4]);
            ah[3] = __float_as_uint(Ahi[r1 + ka + 4]);
            al[0] = __float_as_uint(Alo[r0 + ka]);
            al[1] = __float_as_uint(Alo[r1 + ka]);
            al[2] = __float_as_uint(Alo[r0 + ka + 4]);
            al[3] = __float_as_uint(Alo[r1 + ka + 4]);
            #pragma unroll
            for (int nt = 0; nt < 8; nt++) {
                int nb0 = (kk * 8 + t4) * GB_PITCH + nt * 8 + g;
                int nb1 = (kk * 8 + t4 + 4) * GB_PITCH + nt * 8 + g;
                uint32_t bh0 = __float_as_uint(Bhi[nb0]);
                uint32_t bh1 = __float_as_uint(Bhi[nb1]);
                uint32_t bl0 = __float_as_uint(Blo[nb0]);
                uint32_t bl1 = __float_as_uint(Blo[nb1]);
                mma8(c[nt], ah, bh0, bh1);
                mma8(c[nt], al, bh0, bh1);
                mma8(c[nt], ah, bl0, bl1);
            }
        }
        __syncthreads();
    }

    // ---- epilogue: bias + store ----
    #pragma unroll
    for (int nt = 0; nt < 8; nt++) {
        int col = nBase + nt * 8 + 2 * t4;
        float b0 = bias[col], b1 = bias[col + 1];
        *(float2*)&out[(mBase + m0 + g) * 256 + col] =
            make_float2(c[nt][0] + b0, c[nt][1] + b1);
        *(float2*)&out[(mBase + m0 + g + 8) * 256 + col] =
            make_float2(c[nt][2] + b0, c[nt][3] + b1);
    }
}

// ---------------------------------------------------------------------------
// Flash attention via TF32 mma.sync (m16n8k8)  [unchanged from round 3]
// ---------------------------------------------------------------------------
#define K_PITCH 36
#define V_PITCH 40

__global__ __launch_bounds__(128, 4) void attn_tf32_kernel()
{
    __shared__ float Khi[64 * K_PITCH];
    __shared__ float Klo[64 * K_PITCH];
    __shared__ float Vhi[64 * V_PITCH];
    __shared__ float Vlo[64 * V_PITCH];

    const int tid  = threadIdx.x;
    const int warp = tid >> 5;
    const int lane = tid & 31;
    const int g    = lane >> 2;
    const int t4   = lane & 3;

    const int bh = blockIdx.y;
    const int b  = bh >> 3;
    const int h  = bh & 7;
    const int qBase = blockIdx.x * 64;
    const int q0 = warp * 16;
    const float scale = 0.17677669529663687f;   // 32^-0.5

    uint32_t qh[4][4], ql[4][4];
    {
        const float* qrow0 = &g_Q[((qBase + q0 + g) * B_SZ + b) * E_DIM + h * HD];
        const float* qrow1 = &g_Q[((qBase + q0 + g + 8) * B_SZ + b) * E_DIM + h * HD];
        #pragma unroll
        for (int kk = 0; kk < 4; kk++) {
            int c = kk * 8 + t4;
            float hi, lo;
            split2(qrow0[c] * scale, hi, lo);
            qh[kk][0] = __float_as_uint(hi); ql[kk][0] = __float_as_uint(lo);
            split2(qrow1[c] * scale, hi, lo);
            qh[kk][1] = __float_as_uint(hi); ql[kk][1] = __float_as_uint(lo);
            split2(qrow0[c + 4] * scale, hi, lo);
            qh[kk][2] = __float_as_uint(hi); ql[kk][2] = __float_as_uint(lo);
            split2(qrow1[c + 4] * scale, hi, lo);
            qh[kk][3] = __float_as_uint(hi); ql[kk][3] = __float_as_uint(lo);
        }
    }

    float m0 = -1e30f, m1 = -1e30f, l0 = 0.f, l1 = 0.f;
    float o[4][4];
    #pragma unroll
    for (int n = 0; n < 4; n++)
        o[n][0] = o[n][1] = o[n][2] = o[n][3] = 0.f;

    for (int kt = 0; kt < L_SEQ / 64; kt++) {
        if (kt) __syncthreads();
        for (int idx = tid; idx < 512; idx += 128) {
            int key = idx >> 3, dg = (idx & 7) << 2;
            int grow = ((kt * 64 + key) * B_SZ + b) * E_DIM + h * HD + dg;
            float4 kv = *(const float4*)&g_K[grow];
            float4 vv = *(const float4*)&g_V[grow];
            float4 khf, klf, vhf, vlf;
            split2(kv.x, khf.x, klf.x); split2(kv.y, khf.y, klf.y);
            split2(kv.z, khf.z, klf.z); split2(kv.w, khf.w, klf.w);
            split2(vv.x, vhf.x, vlf.x); split2(vv.y, vhf.y, vlf.y);
            split2(vv.z, vhf.z, vlf.z); split2(vv.w, vhf.w, vlf.w);
            *(float4*)&Khi[key * K_PITCH + dg] = khf;
            *(float4*)&Klo[key * K_PITCH + dg] = klf;
            *(float4*)&Vhi[key * V_PITCH + dg] = vhf;
            *(float4*)&Vlo[key * V_PITCH + dg] = vlf;
        }
        __syncthreads();

        float s[8][4];
        #pragma unroll
        for (int j = 0; j < 8; j++)
            s[j][0] = s[j][1] = s[j][2] = s[j][3] = 0.f;
        #pragma unroll
        for (int j = 0; j < 8; j++) {
            int krow = (j * 8 + g) * K_PITCH;
            #pragma unroll
            for (int kk = 0; kk < 4; kk++) {
                int c = kk * 8 + t4;
                uint32_t kb0 = __float_as_uint(Khi[krow + c]);
                uint32_t kb1 = __float_as_uint(Khi[krow + c + 4]);
                uint32_t lb0 = __float_as_uint(Klo[krow + c]);
                uint32_t lb1 = __float_as_uint(Klo[krow + c + 4]);
                mma8(s[j], qh[kk], kb0, kb1);
                mma8(s[j], ql[kk], kb0, kb1);
                mma8(s[j], qh[kk], lb0, lb1);
            }
        }

        float mx0 = -1e30f, mx1 = -1e30f;
        #pragma unroll
        for (int j = 0; j < 8; j++) {
            mx0 = fmaxf(mx0, fmaxf(s[j][0], s[j][1]));
            mx1 = fmaxf(mx1, fmaxf(s[j][2], s[j][3]));
        }
        mx0 = fmaxf(mx0, __shfl_xor_sync(0xffffffffu, mx0, 1));
        mx0 = fmaxf(mx0, __shfl_xor_sync(0xffffffffu, mx0, 2));
        mx1 = fmaxf(mx1, __shfl_xor_sync(0xffffffffu, mx1, 1));
        mx1 = fmaxf(mx1, __shfl_xor_sync(0xffffffffu, mx1, 2));
        float mn0 = fmaxf(m0, mx0), mn1 = fmaxf(m1, mx1);
        float al0 = __expf(m0 - mn0), al1 = __expf(m1 - mn1);
        float sum0 = 0.f, sum1 = 0.f;
        #pragma unroll
        for (int j = 0; j < 8; j++) {
            s[j][0] = __expf(s[j][0] - mn0);
            s[j][1] = __expf(s[j][1] - mn0);
            sum0 += s[j][0] + s[j][1];
            s[j][2] = __expf(s[j][2] - mn1);
            s[j][3] = __expf(s[j][3] - mn1);
            sum1 += s[j][2] + s[j][3];
        }
        sum0 += __shfl_xor_sync(0xffffffffu, sum0, 1);
        sum0 += __shfl_xor_sync(0xffffffffu, sum0, 2);
        sum1 += __shfl_xor_sync(0xffffffffu, sum1, 1);
        sum1 += __shfl_xor_sync(0xffffffffu, sum1, 2);
        l0 = l0 * al0 + sum0; m0 = mn0;
        l1 = l1 * al1 + sum1; m1 = mn1;
        #pragma unroll
        for (int n = 0; n < 4; n++) {
            o[n][0] *= al0; o[n][1] *= al0;
            o[n][2] *= al1; o[n][3] *= al1;
        }

        #pragma unroll
        for (int ks = 0; ks < 8; ks++) {
            const int hsrc  = (lane & 28) + (t4 >> 1);
            const int hsrc2 = hsrc + 2;
            const bool odd = (t4 & 1);
            float b0 = __shfl_sync(0xffffffffu, s[ks][0], hsrc);
            float b1 = __shfl_sync(0xffffffffu, s[ks][1], hsrc);
            float c0 = __shfl_sync(0xffffffffu, s[ks][2], hsrc);
            float c1 = __shfl_sync(0xffffffffu, s[ks][3], hsrc);
            float d0 = __shfl_sync(0xffffffffu, s[ks][0], hsrc2);
            float d1 = __shfl_sync(0xffffffffu, s[ks][1], hsrc2);
            float e0 = __shfl_sync(0xffffffffu, s[ks][2], hsrc2);
            float e1 = __shfl_sync(0xffffffffu, s[ks][3], hsrc2);
            uint32_t pa[4];
            pa[0] = f2tf(odd ? b1 : b0);
            pa[1] = f2tf(odd ? c1 : c0);
            pa[2] = f2tf(odd ? d1 : d0);
            pa[3] = f2tf(odd ? e1 : e0);

            int vr0 = (ks * 8 + t4) * V_PITCH;
            int vr1 = (ks * 8 + t4 + 4) * V_PITCH;
            #pragma unroll
            for (int n = 0; n < 4; n++) {
                int d0i = n * 8 + g;
                uint32_t vb0 = __float_as_uint(Vhi[vr0 + d0i]);
                uint32_t vb1 = __float_as_uint(Vhi[vr1 + d0i]);
                uint32_t wb0 = __float_as_uint(Vlo[vr0 + d0i]);
                uint32_t wb1 = __float_as_uint(Vlo[vr1 + d0i]);
                mma8(o[n], pa, vb0, vb1);
                mma8(o[n], pa, wb0, wb1);
            }
        }
    }

    float inv0 = 1.0f / l0, inv1 = 1.0f / l1;
    int qr0 = qBase + q0 + g;
    int qr1 = qr0 + 8;
    #pragma unroll
    for (int n = 0; n < 4; n++) {
        int col = h * HD + n * 8 + 2 * t4;
        *(float2*)&g_O[(qr0 * B_SZ + b) * E_DIM + col] =
            make_float2(o[n][0] * inv0, o[n][1] * inv0);
        *(float2*)&g_O[(qr1 * B_SZ + b) * E_DIM + col] =
            make_float2(o[n][2] * inv1, o[n][3] * inv1);
    }
}

// ---------------------------------------------------------------------------
extern "C" void kernel_launch(void* const* d_in, const int* in_sizes, int n_in,
                              void* d_out, int out_size)
{
    const float* query = (const float*)d_in[0];
    const float* key_  = (const float*)d_in[1];
    const float* value = (const float*)d_in[2];
    const float* Wq = (const float*)d_in[3];
    const float* bq = (const float*)d_in[4];
    const float* Wk = (const float*)d_in[5];
    const float* bk = (const float*)d_in[6];
    const float* Wv = (const float*)d_in[7];
    const float* bv = (const float*)d_in[8];
    const float* Wp = (const float*)d_in[9];
    const float* bp = (const float*)d_in[10];
    float* out = (float*)d_out;

    float *qbuf, *kbuf, *vbuf, *obuf;
    cudaGetSymbolAddress((void**)&qbuf, g_Q);
    cudaGetSymbolAddress((void**)&kbuf, g_K);
    cudaGetSymbolAddress((void**)&vbuf, g_V);
    cudaGetSymbolAddress((void**)&obuf, g_O);

    dim3 gg(E_DIM / 64, M_ROWS / 64);   // (4, 64)
    gemm_tf32_kernel<<<gg, 128>>>(query, Wq, bq, qbuf);
    gemm_tf32_kernel<<<gg, 128>>>(key_,  Wk, bk, kbuf);
    gemm_tf32_kernel<<<gg, 128>>>(value, Wv, bv, vbuf);
    attn_tf32_kernel<<<dim3(L_SEQ / 64, B_SZ * NH), 128>>>();
    gemm_tf32_kernel<<<gg, 128>>>(obuf, Wp, bp, out);
}

// round 5
// speedup vs baseline: 1.0668x; 1.0668x over previous
#include <cuda_runtime.h>
#include <math.h>
#include <stdint.h>

#define L_SEQ 2048
#define B_SZ 2
#define E_DIM 256
#define NH 8
#define HD 32
#define M_ROWS (L_SEQ * B_SZ)   // 4096

// Scratch (allocation-free rule: __device__ globals)
static __device__ float g_Q[M_ROWS * E_DIM];
static __device__ float g_K[M_ROWS * E_DIM];
static __device__ float g_V[M_ROWS * E_DIM];
static __device__ float g_O[M_ROWS * E_DIM];

// ---------------------------------------------------------------------------
// helpers: tf32 convert / hi-lo split / mma (NON-volatile: pure register
// dataflow -> compiler/ptxas free to interleave independent mma chains)
// ---------------------------------------------------------------------------
__device__ __forceinline__ uint32_t f2tf(float x) {
    uint32_t r; asm("cvt.rna.tf32.f32 %0, %1;" : "=r"(r) : "f"(x)); return r;
}
__device__ __forceinline__ void split2(float x, float& hi, float& lo) {
    uint32_t h = f2tf(x);
    hi = __uint_as_float(h);
    lo = __uint_as_float(f2tf(x - hi));
}
__device__ __forceinline__ void mma8(float c[4], const uint32_t a[4],
                                     uint32_t b0, uint32_t b1) {
    asm("mma.sync.aligned.m16n8k8.row.col.f32.tf32.tf32.f32 "
        "{%0,%1,%2,%3}, {%4,%5,%6,%7}, {%8,%9}, {%0,%1,%2,%3};"
        : "+f"(c[0]), "+f"(c[1]), "+f"(c[2]), "+f"(c[3])
        : "r"(a[0]), "r"(a[1]), "r"(a[2]), "r"(a[3]), "r"(b0), "r"(b1));
}

// ---------------------------------------------------------------------------
// GEMM: out[M,N] = X[M,256] @ W[256,N] + bias[N]  (fp32 SIMT, round-1 proven)
// ---------------------------------------------------------------------------
__global__ __launch_bounds__(256) void gemm_bias_kernel(
    const float* __restrict__ X, const float* __restrict__ W,
    const float* __restrict__ bias, float* __restrict__ out)
{
    __shared__ float As[16][68];
    __shared__ float Bs[16][68];

    const int tid = threadIdx.x;
    const int tx  = tid & 15;
    const int ty  = tid >> 4;
    const int mBase = blockIdx.y * 64;
    const int nBase = blockIdx.x * 64;

    const int lr = tid >> 2;
    const int lk = (tid & 3) << 2;
    const int wr = tid >> 4;
    const int wn = (tid & 15) << 2;

    float c[4][4] = {};

    for (int k0 = 0; k0 < 256; k0 += 16) {
        float4 a = *(const float4*)&X[(mBase + lr) * 256 + k0 + lk];
        As[lk + 0][lr] = a.x; As[lk + 1][lr] = a.y;
        As[lk + 2][lr] = a.z; As[lk + 3][lr] = a.w;
        float4 bvec = *(const float4*)&W[(k0 + wr) * 256 + nBase + wn];
        *(float4*)&Bs[wr][wn] = bvec;
        __syncthreads();

        #pragma unroll
        for (int k = 0; k < 16; k++) {
            float4 av = *(float4*)&As[k][ty * 4];
            float4 bv = *(float4*)&Bs[k][tx * 4];
            float ar[4] = {av.x, av.y, av.z, av.w};
            float br[4] = {bv.x, bv.y, bv.z, bv.w};
            #pragma unroll
            for (int i = 0; i < 4; i++)
                #pragma unroll
                for (int j = 0; j < 4; j++)
                    c[i][j] += ar[i] * br[j];
        }
        __syncthreads();
    }

    float4 bb = *(const float4*)&bias[nBase + tx * 4];
    float bl[4] = {bb.x, bb.y, bb.z, bb.w};
    #pragma unroll
    for (int i = 0; i < 4; i++) {
        float4 o;
        o.x = c[i][0] + bl[0];
        o.y = c[i][1] + bl[1];
        o.z = c[i][2] + bl[2];
        o.w = c[i][3] + bl[3];
        *(float4*)&out[(mBase + ty * 4 + i) * 256 + nBase + tx * 4] = o;
    }
}

// ---------------------------------------------------------------------------
// Flash attention via TF32 mma.sync (m16n8k8).
// CTA = 128 threads (4 warps), BQ=64, BK=64, D=32. Grid (32, 16).
// QK^T: 3-term tf32 split. PV: P tf32-rounded, V hi/lo (2 mmas).
// mma asm is non-volatile -> scheduler interleaves the 8 s[j] / 4 o[n]
// accumulation chains across the HMMA latency.
// ---------------------------------------------------------------------------
#define K_PITCH 36
#define V_PITCH 40

__global__ __launch_bounds__(128, 4) void attn_tf32_kernel()
{
    __shared__ float Khi[64 * K_PITCH];
    __shared__ float Klo[64 * K_PITCH];
    __shared__ float Vhi[64 * V_PITCH];
    __shared__ float Vlo[64 * V_PITCH];

    const int tid  = threadIdx.x;
    const int warp = tid >> 5;
    const int lane = tid & 31;
    const int g    = lane >> 2;
    const int t4   = lane & 3;

    const int bh = blockIdx.y;
    const int b  = bh >> 3;
    const int h  = bh & 7;
    const int qBase = blockIdx.x * 64;
    const int q0 = warp * 16;
    const float scale = 0.17677669529663687f;   // 32^-0.5

    uint32_t qh[4][4], ql[4][4];
    {
        const float* qrow0 = &g_Q[((qBase + q0 + g) * B_SZ + b) * E_DIM + h * HD];
        const float* qrow1 = &g_Q[((qBase + q0 + g + 8) * B_SZ + b) * E_DIM + h * HD];
        #pragma unroll
        for (int kk = 0; kk < 4; kk++) {
            int c = kk * 8 + t4;
            float hi, lo;
            split2(qrow0[c] * scale, hi, lo);
            qh[kk][0] = __float_as_uint(hi); ql[kk][0] = __float_as_uint(lo);
            split2(qrow1[c] * scale, hi, lo);
            qh[kk][1] = __float_as_uint(hi); ql[kk][1] = __float_as_uint(lo);
            split2(qrow0[c + 4] * scale, hi, lo);
            qh[kk][2] = __float_as_uint(hi); ql[kk][2] = __float_as_uint(lo);
            split2(qrow1[c + 4] * scale, hi, lo);
            qh[kk][3] = __float_as_uint(hi); ql[kk][3] = __float_as_uint(lo);
        }
    }

    float m0 = -1e30f, m1 = -1e30f, l0 = 0.f, l1 = 0.f;
    float o[4][4];
    #pragma unroll
    for (int n = 0; n < 4; n++)
        o[n][0] = o[n][1] = o[n][2] = o[n][3] = 0.f;

    for (int kt = 0; kt < L_SEQ / 64; kt++) {
        if (kt) __syncthreads();
        // ---- load + split K,V tile ----
        for (int idx = tid; idx < 512; idx += 128) {
            int key = idx >> 3, dg = (idx & 7) << 2;
            int grow = ((kt * 64 + key) * B_SZ + b) * E_DIM + h * HD + dg;
            float4 kv = *(const float4*)&g_K[grow];
            float4 vv = *(const float4*)&g_V[grow];
            float4 khf, klf, vhf, vlf;
            split2(kv.x, khf.x, klf.x); split2(kv.y, khf.y, klf.y);
            split2(kv.z, khf.z, klf.z); split2(kv.w, khf.w, klf.w);
            split2(vv.x, vhf.x, vlf.x); split2(vv.y, vhf.y, vlf.y);
            split2(vv.z, vhf.z, vlf.z); split2(vv.w, vhf.w, vlf.w);
            *(float4*)&Khi[key * K_PITCH + dg] = khf;
            *(float4*)&Klo[key * K_PITCH + dg] = klf;
            *(float4*)&Vhi[key * V_PITCH + dg] = vhf;
            *(float4*)&Vlo[key * V_PITCH + dg] = vlf;
        }
        __syncthreads();

        // ---- S = Q K^T (3xTF32) ----
        float s[8][4];
        #pragma unroll
        for (int j = 0; j < 8; j++)
            s[j][0] = s[j][1] = s[j][2] = s[j][3] = 0.f;
        #pragma unroll
        for (int kk = 0; kk < 4; kk++) {
            #pragma unroll
            for (int j = 0; j < 8; j++) {
                int krow = (j * 8 + g) * K_PITCH;
                int c = kk * 8 + t4;
                uint32_t kb0 = __float_as_uint(Khi[krow + c]);
                uint32_t kb1 = __float_as_uint(Khi[krow + c + 4]);
                uint32_t lb0 = __float_as_uint(Klo[krow + c]);
                uint32_t lb1 = __float_as_uint(Klo[krow + c + 4]);
                mma8(s[j], qh[kk], kb0, kb1);
                mma8(s[j], ql[kk], kb0, kb1);
                mma8(s[j], qh[kk], lb0, lb1);
            }
        }

        // ---- online softmax ----
        float mx0 = -1e30f, mx1 = -1e30f;
        #pragma unroll
        for (int j = 0; j < 8; j++) {
            mx0 = fmaxf(mx0, fmaxf(s[j][0], s[j][1]));
            mx1 = fmaxf(mx1, fmaxf(s[j][2], s[j][3]));
        }
        mx0 = fmaxf(mx0, __shfl_xor_sync(0xffffffffu, mx0, 1));
        mx0 = fmaxf(mx0, __shfl_xor_sync(0xffffffffu, mx0, 2));
        mx1 = fmaxf(mx1, __shfl_xor_sync(0xffffffffu, mx1, 1));
        mx1 = fmaxf(mx1, __shfl_xor_sync(0xffffffffu, mx1, 2));
        float mn0 = fmaxf(m0, mx0), mn1 = fmaxf(m1, mx1);
        float al0 = __expf(m0 - mn0), al1 = __expf(m1 - mn1);
        float sum0 = 0.f, sum1 = 0.f;
        #pragma unroll
        for (int j = 0; j < 8; j++) {
            s[j][0] = __expf(s[j][0] - mn0);
            s[j][1] = __expf(s[j][1] - mn0);
            sum0 += s[j][0] + s[j][1];
            s[j][2] = __expf(s[j][2] - mn1);
            s[j][3] = __expf(s[j][3] - mn1);
            sum1 += s[j][2] + s[j][3];
        }
        sum0 += __shfl_xor_sync(0xffffffffu, sum0, 1);
        sum0 += __shfl_xor_sync(0xffffffffu, sum0, 2);
        sum1 += __shfl_xor_sync(0xffffffffu, sum1, 1);
        sum1 += __shfl_xor_sync(0xffffffffu, sum1, 2);
        l0 = l0 * al0 + sum0; m0 = mn0;
        l1 = l1 * al1 + sum1; m1 = mn1;
        #pragma unroll
        for (int n = 0; n < 4; n++) {
            o[n][0] *= al0; o[n][1] *= al0;
            o[n][2] *= al1; o[n][3] *= al1;
        }

        // ---- O += P V : C-frag -> A-frag via intra-quad shuffles ----
        #pragma unroll
        for (int ks = 0; ks < 8; ks++) {
            const int hsrc  = (lane & 28) + (t4 >> 1);
            const int hsrc2 = hsrc + 2;
            const bool odd = (t4 & 1);
            float b0 = __shfl_sync(0xffffffffu, s[ks][0], hsrc);
            float b1 = __shfl_sync(0xffffffffu, s[ks][1], hsrc);
            float c0 = __shfl_sync(0xffffffffu, s[ks][2], hsrc);
            float c1 = __shfl_sync(0xffffffffu, s[ks][3], hsrc);
            float d0 = __shfl_sync(0xffffffffu, s[ks][0], hsrc2);
            float d1 = __shfl_sync(0xffffffffu, s[ks][1], hsrc2);
            float e0 = __shfl_sync(0xffffffffu, s[ks][2], hsrc2);
            float e1 = __shfl_sync(0xffffffffu, s[ks][3], hsrc2);
            uint32_t pa[4];
            pa[0] = f2tf(odd ? b1 : b0);
            pa[1] = f2tf(odd ? c1 : c0);
            pa[2] = f2tf(odd ? d1 : d0);
            pa[3] = f2tf(odd ? e1 : e0);

            int vr0 = (ks * 8 + t4) * V_PITCH;
            int vr1 = (ks * 8 + t4 + 4) * V_PITCH;
            // hi terms for all n, then lo terms: dependent pairs 4 apart
            uint32_t vb0[4], vb1[4], wb0[4], wb1[4];
            #pragma unroll
            for (int n = 0; n < 4; n++) {
                int d0i = n * 8 + g;
                vb0[n] = __float_as_uint(Vhi[vr0 + d0i]);
                vb1[n] = __float_as_uint(Vhi[vr1 + d0i]);
                wb0[n] = __float_as_uint(Vlo[vr0 + d0i]);
                wb1[n] = __float_as_uint(Vlo[vr1 + d0i]);
            }
            #pragma unroll
            for (int n = 0; n < 4; n++)
                mma8(o[n], pa, vb0[n], vb1[n]);
            #pragma unroll
            for (int n = 0; n < 4; n++)
                mma8(o[n], pa, wb0[n], wb1[n]);
        }
    }

    // ---- epilogue ----
    float inv0 = 1.0f / l0, inv1 = 1.0f / l1;
    int qr0 = qBase + q0 + g;
    int qr1 = qr0 + 8;
    #pragma unroll
    for (int n = 0; n < 4; n++) {
        int col = h * HD + n * 8 + 2 * t4;
        *(float2*)&g_O[(qr0 * B_SZ + b) * E_DIM + col] =
            make_float2(o[n][0] * inv0, o[n][1] * inv0);
        *(float2*)&g_O[(qr1 * B_SZ + b) * E_DIM + col] =
            make_float2(o[n][2] * inv1, o[n][3] * inv1);
    }
}

// ---------------------------------------------------------------------------
extern "C" void kernel_launch(void* const* d_in, const int* in_sizes, int n_in,
                              void* d_out, int out_size)
{
    const float* query = (const float*)d_in[0];
    const float* key_  = (const float*)d_in[1];
    const float* value = (const float*)d_in[2];
    const float* Wq = (const float*)d_in[3];
    const float* bq = (const float*)d_in[4];
    const float* Wk = (const float*)d_in[5];
    const float* bk = (const float*)d_in[6];
    const float* Wv = (const float*)d_in[7];
    const float* bv = (const float*)d_in[8];
    const float* Wp = (const float*)d_in[9];
    const float* bp = (const float*)d_in[10];
    float* out = (float*)d_out;

    float *qbuf, *kbuf, *vbuf, *obuf;
    cudaGetSymbolAddress((void**)&qbuf, g_Q);
    cudaGetSymbolAddress((void**)&kbuf, g_K);
    cudaGetSymbolAddress((void**)&vbuf, g_V);
    cudaGetSymbolAddress((void**)&obuf, g_O);

    dim3 gg(E_DIM / 64, M_ROWS / 64);   // (4, 64)
    gemm_bias_kernel<<<gg, 256>>>(query, Wq, bq, qbuf);
    gemm_bias_kernel<<<gg, 256>>>(key_,  Wk, bk, kbuf);
    gemm_bias_kernel<<<gg, 256>>>(value, Wv, bv, vbuf);
    attn_tf32_kernel<<<dim3(L_SEQ / 64, B_SZ * NH), 128>>>();
    gemm_bias_kernel<<<gg, 256>>>(obuf, Wp, bp, out);
}

// round 6
// speedup vs baseline: 1.0671x; 1.0003x over previous
#include <cuda_runtime.h>
#include <math.h>
#include <stdint.h>

#define L_SEQ 2048
#define B_SZ 2
#define E_DIM 256
#define NH 8
#define HD 32
#define M_ROWS (L_SEQ * B_SZ)   // 4096

// Scratch (allocation-free rule: __device__ globals)
static __device__ float g_Q[M_ROWS * E_DIM];
static __device__ float g_K[M_ROWS * E_DIM];
static __device__ float g_V[M_ROWS * E_DIM];
static __device__ float g_O[M_ROWS * E_DIM];

// ---------------------------------------------------------------------------
// helpers: tf32 convert / hi-lo split / mma (NON-volatile: pure register
// dataflow -> compiler/ptxas free to interleave independent mma chains)
// ---------------------------------------------------------------------------
__device__ __forceinline__ uint32_t f2tf(float x) {
    uint32_t r; asm("cvt.rna.tf32.f32 %0, %1;" : "=r"(r) : "f"(x)); return r;
}
__device__ __forceinline__ void split2(float x, float& hi, float& lo) {
    uint32_t h = f2tf(x);
    hi = __uint_as_float(h);
    lo = __uint_as_float(f2tf(x - hi));
}
__device__ __forceinline__ void mma8(float c[4], const uint32_t a[4],
                                     uint32_t b0, uint32_t b1) {
    asm("mma.sync.aligned.m16n8k8.row.col.f32.tf32.tf32.f32 "
        "{%0,%1,%2,%3}, {%4,%5,%6,%7}, {%8,%9}, {%0,%1,%2,%3};"
        : "+f"(c[0]), "+f"(c[1]), "+f"(c[2]), "+f"(c[3])
        : "r"(a[0]), "r"(a[1]), "r"(a[2]), "r"(a[3]), "r"(b0), "r"(b1));
}

// ---------------------------------------------------------------------------
// GEMM: out[M,N] = X[M,256] @ W[256,N] + bias[N]  (fp32 SIMT, round-1 proven)
// ---------------------------------------------------------------------------
__global__ __launch_bounds__(256) void gemm_bias_kernel(
    const float* __restrict__ X, const float* __restrict__ W,
    const float* __restrict__ bias, float* __restrict__ out)
{
    __shared__ float As[16][68];
    __shared__ float Bs[16][68];

    const int tid = threadIdx.x;
    const int tx  = tid & 15;
    const int ty  = tid >> 4;
    const int mBase = blockIdx.y * 64;
    const int nBase = blockIdx.x * 64;

    const int lr = tid >> 2;
    const int lk = (tid & 3) << 2;
    const int wr = tid >> 4;
    const int wn = (tid & 15) << 2;

    float c[4][4] = {};

    for (int k0 = 0; k0 < 256; k0 += 16) {
        float4 a = *(const float4*)&X[(mBase + lr) * 256 + k0 + lk];
        As[lk + 0][lr] = a.x; As[lk + 1][lr] = a.y;
        As[lk + 2][lr] = a.z; As[lk + 3][lr] = a.w;
        float4 bvec = *(const float4*)&W[(k0 + wr) * 256 + nBase + wn];
        *(float4*)&Bs[wr][wn] = bvec;
        __syncthreads();

        #pragma unroll
        for (int k = 0; k < 16; k++) {
            float4 av = *(float4*)&As[k][ty * 4];
            float4 bv = *(float4*)&Bs[k][tx * 4];
            float ar[4] = {av.x, av.y, av.z, av.w};
            float br[4] = {bv.x, bv.y, bv.z, bv.w};
            #pragma unroll
            for (int i = 0; i < 4; i++)
                #pragma unroll
                for (int j = 0; j < 4; j++)
                    c[i][j] += ar[i] * br[j];
        }
        __syncthreads();
    }

    float4 bb = *(const float4*)&bias[nBase + tx * 4];
    float bl[4] = {bb.x, bb.y, bb.z, bb.w};
    #pragma unroll
    for (int i = 0; i < 4; i++) {
        float4 o;
        o.x = c[i][0] + bl[0];
        o.y = c[i][1] + bl[1];
        o.z = c[i][2] + bl[2];
        o.w = c[i][3] + bl[3];
        *(float4*)&out[(mBase + ty * 4 + i) * 256 + nBase + tx * 4] = o;
    }
}

// ---------------------------------------------------------------------------
// Flash attention via TF32 mma.sync (m16n8k8).
// CTA = 128 threads (4 warps), BQ=64, BK=64, D=32. Grid (32, 16).
// QK^T: 3-term tf32 split. PV: P tf32-rounded, V hi/lo (2 mmas).
// mma asm is non-volatile -> scheduler interleaves the 8 s[j] / 4 o[n]
// accumulation chains across the HMMA latency.
// ---------------------------------------------------------------------------
#define K_PITCH 36
#define V_PITCH 40

__global__ __launch_bounds__(128, 4) void attn_tf32_kernel()
{
    __shared__ float Khi[64 * K_PITCH];
    __shared__ float Klo[64 * K_PITCH];
    __shared__ float Vhi[64 * V_PITCH];
    __shared__ float Vlo[64 * V_PITCH];

    const int tid  = threadIdx.x;
    const int warp = tid >> 5;
    const int lane = tid & 31;
    const int g    = lane >> 2;
    const int t4   = lane & 3;

    const int bh = blockIdx.y;
    const int b  = bh >> 3;
    const int h  = bh & 7;
    const int qBase = blockIdx.x * 64;
    const int q0 = warp * 16;
    const float scale = 0.17677669529663687f;   // 32^-0.5

    uint32_t qh[4][4], ql[4][4];
    {
        const float* qrow0 = &g_Q[((qBase + q0 + g) * B_SZ + b) * E_DIM + h * HD];
        const float* qrow1 = &g_Q[((qBase + q0 + g + 8) * B_SZ + b) * E_DIM + h * HD];
        #pragma unroll
        for (int kk = 0; kk < 4; kk++) {
            int c = kk * 8 + t4;
            float hi, lo;
            split2(qrow0[c] * scale, hi, lo);
            qh[kk][0] = __float_as_uint(hi); ql[kk][0] = __float_as_uint(lo);
            split2(qrow1[c] * scale, hi, lo);
            qh[kk][1] = __float_as_uint(hi); ql[kk][1] = __float_as_uint(lo);
            split2(qrow0[c + 4] * scale, hi, lo);
            qh[kk][2] = __float_as_uint(hi); ql[kk][2] = __float_as_uint(lo);
            split2(qrow1[c + 4] * scale, hi, lo);
            qh[kk][3] = __float_as_uint(hi); ql[kk][3] = __float_as_uint(lo);
        }
    }

    float m0 = -1e30f, m1 = -1e30f, l0 = 0.f, l1 = 0.f;
    float o[4][4];
    #pragma unroll
    for (int n = 0; n < 4; n++)
        o[n][0] = o[n][1] = o[n][2] = o[n][3] = 0.f;

    for (int kt = 0; kt < L_SEQ / 64; kt++) {
        if (kt) __syncthreads();
        // ---- load + split K,V tile ----
        for (int idx = tid; idx < 512; idx += 128) {
            int key = idx >> 3, dg = (idx & 7) << 2;
            int grow = ((kt * 64 + key) * B_SZ + b) * E_DIM + h * HD + dg;
            float4 kv = *(const float4*)&g_K[grow];
            float4 vv = *(const float4*)&g_V[grow];
            float4 khf, klf, vhf, vlf;
            split2(kv.x, khf.x, klf.x); split2(kv.y, khf.y, klf.y);
            split2(kv.z, khf.z, klf.z); split2(kv.w, khf.w, klf.w);
            split2(vv.x, vhf.x, vlf.x); split2(vv.y, vhf.y, vlf.y);
            split2(vv.z, vhf.z, vlf.z); split2(vv.w, vhf.w, vlf.w);
            *(float4*)&Khi[key * K_PITCH + dg] = khf;
            *(float4*)&Klo[key * K_PITCH + dg] = klf;
            *(float4*)&Vhi[key * V_PITCH + dg] = vhf;
            *(float4*)&Vlo[key * V_PITCH + dg] = vlf;
        }
        __syncthreads();

        // ---- S = Q K^T (3xTF32) ----
        float s[8][4];
        #pragma unroll
        for (int j = 0; j < 8; j++)
            s[j][0] = s[j][1] = s[j][2] = s[j][3] = 0.f;
        #pragma unroll
        for (int kk = 0; kk < 4; kk++) {
            #pragma unroll
            for (int j = 0; j < 8; j++) {
                int krow = (j * 8 + g) * K_PITCH;
                int c = kk * 8 + t4;
                uint32_t kb0 = __float_as_uint(Khi[krow + c]);
                uint32_t kb1 = __float_as_uint(Khi[krow + c + 4]);
                uint32_t lb0 = __float_as_uint(Klo[krow + c]);
                uint32_t lb1 = __float_as_uint(Klo[krow + c + 4]);
                mma8(s[j], qh[kk], kb0, kb1);
                mma8(s[j], ql[kk], kb0, kb1);
                mma8(s[j], qh[kk], lb0, lb1);
            }
        }

        // ---- online softmax ----
        float mx0 = -1e30f, mx1 = -1e30f;
        #pragma unroll
        for (int j = 0; j < 8; j++) {
            mx0 = fmaxf(mx0, fmaxf(s[j][0], s[j][1]));
            mx1 = fmaxf(mx1, fmaxf(s[j][2], s[j][3]));
        }
        mx0 = fmaxf(mx0, __shfl_xor_sync(0xffffffffu, mx0, 1));
        mx0 = fmaxf(mx0, __shfl_xor_sync(0xffffffffu, mx0, 2));
        mx1 = fmaxf(mx1, __shfl_xor_sync(0xffffffffu, mx1, 1));
        mx1 = fmaxf(mx1, __shfl_xor_sync(0xffffffffu, mx1, 2));
        float mn0 = fmaxf(m0, mx0), mn1 = fmaxf(m1, mx1);
        float al0 = __expf(m0 - mn0), al1 = __expf(m1 - mn1);
        float sum0 = 0.f, sum1 = 0.f;
        #pragma unroll
        for (int j = 0; j < 8; j++) {
            s[j][0] = __expf(s[j][0] - mn0);
            s[j][1] = __expf(s[j][1] - mn0);
            sum0 += s[j][0] + s[j][1];
            s[j][2] = __expf(s[j][2] - mn1);
            s[j][3] = __expf(s[j][3] - mn1);
            sum1 += s[j][2] + s[j][3];
        }
        sum0 += __shfl_xor_sync(0xffffffffu, sum0, 1);
        sum0 += __shfl_xor_sync(0xffffffffu, sum0, 2);
        sum1 += __shfl_xor_sync(0xffffffffu, sum1, 1);
        sum1 += __shfl_xor_sync(0xffffffffu, sum1, 2);
        l0 = l0 * al0 + sum0; m0 = mn0;
        l1 = l1 * al1 + sum1; m1 = mn1;
        #pragma unroll
        for (int n = 0; n < 4; n++) {
            o[n][0] *= al0; o[n][1] *= al0;
            o[n][2] *= al1; o[n][3] *= al1;
        }

        // ---- O += P V : C-frag -> A-frag via intra-quad shuffles ----
        #pragma unroll
        for (int ks = 0; ks < 8; ks++) {
            const int hsrc  = (lane & 28) + (t4 >> 1);
            const int hsrc2 = hsrc + 2;
            const bool odd = (t4 & 1);
            float b0 = __shfl_sync(0xffffffffu, s[ks][0], hsrc);
            float b1 = __shfl_sync(0xffffffffu, s[ks][1], hsrc);
            float c0 = __shfl_sync(0xffffffffu, s[ks][2], hsrc);
            float c1 = __shfl_sync(0xffffffffu, s[ks][3], hsrc);
            float d0 = __shfl_sync(0xffffffffu, s[ks][0], hsrc2);
            float d1 = __shfl_sync(0xffffffffu, s[ks][1], hsrc2);
            float e0 = __shfl_sync(0xffffffffu, s[ks][2], hsrc2);
            float e1 = __shfl_sync(0xffffffffu, s[ks][3], hsrc2);
            uint32_t pa[4];
            pa[0] = f2tf(odd ? b1 : b0);
            pa[1] = f2tf(odd ? c1 : c0);
            pa[2] = f2tf(odd ? d1 : d0);
            pa[3] = f2tf(odd ? e1 : e0);

            int vr0 = (ks * 8 + t4) * V_PITCH;
            int vr1 = (ks * 8 + t4 + 4) * V_PITCH;
            // hi terms for all n, then lo terms: dependent pairs 4 apart
            uint32_t vb0[4], vb1[4], wb0[4], wb1[4];
            #pragma unroll
            for (int n = 0; n < 4; n++) {
                int d0i = n * 8 + g;
                vb0[n] = __float_as_uint(Vhi[vr0 + d0i]);
                vb1[n] = __float_as_uint(Vhi[vr1 + d0i]);
                wb0[n] = __float_as_uint(Vlo[vr0 + d0i]);
                wb1[n] = __float_as_uint(Vlo[vr1 + d0i]);
            }
            #pragma unroll
            for (int n = 0; n < 4; n++)
                mma8(o[n], pa, vb0[n], vb1[n]);
            #pragma unroll
            for (int n = 0; n < 4; n++)
                mma8(o[n], pa, wb0[n], wb1[n]);
        }
    }

    // ---- epilogue ----
    float inv0 = 1.0f / l0, inv1 = 1.0f / l1;
    int qr0 = qBase + q0 + g;
    int qr1 = qr0 + 8;
    #pragma unroll
    for (int n = 0; n < 4; n++) {
        int col = h * HD + n * 8 + 2 * t4;
        *(float2*)&g_O[(qr0 * B_SZ + b) * E_DIM + col] =
            make_float2(o[n][0] * inv0, o[n][1] * inv0);
        *(float2*)&g_O[(qr1 * B_SZ + b) * E_DIM + col] =
            make_float2(o[n][2] * inv1, o[n][3] * inv1);
    }
}

// ---------------------------------------------------------------------------
extern "C" void kernel_launch(void* const* d_in, const int* in_sizes, int n_in,
                              void* d_out, int out_size)
{
    const float* query = (const float*)d_in[0];
    const float* key_  = (const float*)d_in[1];
    const float* value = (const float*)d_in[2];
    const float* Wq = (const float*)d_in[3];
    const float* bq = (const float*)d_in[4];
    const float* Wk = (const float*)d_in[5];
    const float* bk = (const float*)d_in[6];
    const float* Wv = (const float*)d_in[7];
    const float* bv = (const float*)d_in[8];
    const float* Wp = (const float*)d_in[9];
    const float* bp = (const float*)d_in[10];
    float* out = (float*)d_out;

    float *qbuf, *kbuf, *vbuf, *obuf;
    cudaGetSymbolAddress((void**)&qbuf, g_Q);
    cudaGetSymbolAddress((void**)&kbuf, g_K);
    cudaGetSymbolAddress((void**)&vbuf, g_V);
    cudaGetSymbolAddress((void**)&obuf, g_O);

    dim3 gg(E_DIM / 64, M_ROWS / 64);   // (4, 64)
    gemm_bias_kernel<<<gg, 256>>>(query, Wq, bq, qbuf);
    gemm_bias_kernel<<<gg, 256>>>(key_,  Wk, bk, kbuf);
    gemm_bias_kernel<<<gg, 256>>>(value, Wv, bv, vbuf);
    attn_tf32_kernel<<<dim3(L_SEQ / 64, B_SZ * NH), 128>>>();
    gemm_bias_kernel<<<gg, 256>>>(obuf, Wp, bp, out);
}

// round 7
// speedup vs baseline: 1.1336x; 1.0623x over previous
#include <cuda_runtime.h>
#include <math.h>
#include <stdint.h>

#define L_SEQ 2048
#define B_SZ 2
#define E_DIM 256
#define NH 8
#define HD 32
#define M_ROWS (L_SEQ * B_SZ)   // 4096
#define NSPLIT 2
#define BHL (NH * B_SZ * L_SEQ) // 32768 (bh, q) rows

// Scratch (allocation-free rule: __device__ globals)
static __device__ float g_Q[M_ROWS * E_DIM];
static __device__ float g_K[M_ROWS * E_DIM];
static __device__ float g_V[M_ROWS * E_DIM];
static __device__ float g_O[M_ROWS * E_DIM];
// split-K partials: o (unnormalized), m, l per (z, bh, q)
static __device__ float g_Po[NSPLIT * BHL * HD];
static __device__ float g_Pm[NSPLIT * BHL];
static __device__ float g_Pl[NSPLIT * BHL];

// ---------------------------------------------------------------------------
// helpers: tf32 convert / hi-lo split / mma
// ---------------------------------------------------------------------------
__device__ __forceinline__ uint32_t f2tf(float x) {
    uint32_t r; asm("cvt.rna.tf32.f32 %0, %1;" : "=r"(r) : "f"(x)); return r;
}
__device__ __forceinline__ void split2(float x, float& hi, float& lo) {
    uint32_t h = f2tf(x);
    hi = __uint_as_float(h);
    lo = __uint_as_float(f2tf(x - hi));
}
__device__ __forceinline__ void mma8(float c[4], const uint32_t a[4],
                                     uint32_t b0, uint32_t b1) {
    asm("mma.sync.aligned.m16n8k8.row.col.f32.tf32.tf32.f32 "
        "{%0,%1,%2,%3}, {%4,%5,%6,%7}, {%8,%9}, {%0,%1,%2,%3};"
        : "+f"(c[0]), "+f"(c[1]), "+f"(c[2]), "+f"(c[3])
        : "r"(a[0]), "r"(a[1]), "r"(a[2]), "r"(a[3]), "r"(b0), "r"(b1));
}

// ---------------------------------------------------------------------------
// GEMM: out[M,N] = X[M,256] @ W[256,N] + bias[N]  (fp32 SIMT, proven)
// ---------------------------------------------------------------------------
__global__ __launch_bounds__(256) void gemm_bias_kernel(
    const float* __restrict__ X, const float* __restrict__ W,
    const float* __restrict__ bias, float* __restrict__ out)
{
    __shared__ float As[16][68];
    __shared__ float Bs[16][68];

    const int tid = threadIdx.x;
    const int tx  = tid & 15;
    const int ty  = tid >> 4;
    const int mBase = blockIdx.y * 64;
    const int nBase = blockIdx.x * 64;

    const int lr = tid >> 2;
    const int lk = (tid & 3) << 2;
    const int wr = tid >> 4;
    const int wn = (tid & 15) << 2;

    float c[4][4] = {};

    for (int k0 = 0; k0 < 256; k0 += 16) {
        float4 a = *(const float4*)&X[(mBase + lr) * 256 + k0 + lk];
        As[lk + 0][lr] = a.x; As[lk + 1][lr] = a.y;
        As[lk + 2][lr] = a.z; As[lk + 3][lr] = a.w;
        float4 bvec = *(const float4*)&W[(k0 + wr) * 256 + nBase + wn];
        *(float4*)&Bs[wr][wn] = bvec;
        __syncthreads();

        #pragma unroll
        for (int k = 0; k < 16; k++) {
            float4 av = *(float4*)&As[k][ty * 4];
            float4 bv = *(float4*)&Bs[k][tx * 4];
            float ar[4] = {av.x, av.y, av.z, av.w};
            float br[4] = {bv.x, bv.y, bv.z, bv.w};
            #pragma unroll
            for (int i = 0; i < 4; i++)
                #pragma unroll
                for (int j = 0; j < 4; j++)
                    c[i][j] += ar[i] * br[j];
        }
        __syncthreads();
    }

    float4 bb = *(const float4*)&bias[nBase + tx * 4];
    float bl[4] = {bb.x, bb.y, bb.z, bb.w};
    #pragma unroll
    for (int i = 0; i < 4; i++) {
        float4 o;
        o.x = c[i][0] + bl[0];
        o.y = c[i][1] + bl[1];
        o.z = c[i][2] + bl[2];
        o.w = c[i][3] + bl[3];
        *(float4*)&out[(mBase + ty * 4 + i) * 256 + nBase + tx * 4] = o;
    }
}

// ---------------------------------------------------------------------------
// Flash attention via TF32 mma.sync (m16n8k8), SPLIT-K over blockIdx.z.
// CTA: 128 threads (4 warps), BQ=64, BK=64. Grid (32, 16, 2) = 1024 CTAs.
// Each z-half covers 1024 keys (16 tiles) and emits unnormalized partials.
// ---------------------------------------------------------------------------
#define K_PITCH 36
#define V_PITCH 40
#define KT_PER_SPLIT (L_SEQ / 64 / NSPLIT)   // 16

__global__ __launch_bounds__(128, 4) void attn_tf32_kernel()
{
    __shared__ float Khi[64 * K_PITCH];
    __shared__ float Klo[64 * K_PITCH];
    __shared__ float Vhi[64 * V_PITCH];
    __shared__ float Vlo[64 * V_PITCH];

    const int tid  = threadIdx.x;
    const int warp = tid >> 5;
    const int lane = tid & 31;
    const int g    = lane >> 2;
    const int t4   = lane & 3;

    const int bh = blockIdx.y;
    const int z  = blockIdx.z;
    const int b  = bh >> 3;
    const int h  = bh & 7;
    const int qBase = blockIdx.x * 64;
    const int q0 = warp * 16;
    const float scale = 0.17677669529663687f;   // 32^-0.5

    uint32_t qh[4][4], ql[4][4];
    {
        const float* qrow0 = &g_Q[((qBase + q0 + g) * B_SZ + b) * E_DIM + h * HD];
        const float* qrow1 = &g_Q[((qBase + q0 + g + 8) * B_SZ + b) * E_DIM + h * HD];
        #pragma unroll
        for (int kk = 0; kk < 4; kk++) {
            int c = kk * 8 + t4;
            float hi, lo;
            split2(qrow0[c] * scale, hi, lo);
            qh[kk][0] = __float_as_uint(hi); ql[kk][0] = __float_as_uint(lo);
            split2(qrow1[c] * scale, hi, lo);
            qh[kk][1] = __float_as_uint(hi); ql[kk][1] = __float_as_uint(lo);
            split2(qrow0[c + 4] * scale, hi, lo);
            qh[kk][2] = __float_as_uint(hi); ql[kk][2] = __float_as_uint(lo);
            split2(qrow1[c + 4] * scale, hi, lo);
            qh[kk][3] = __float_as_uint(hi); ql[kk][3] = __float_as_uint(lo);
        }
    }

    float m0 = -1e30f, m1 = -1e30f, l0 = 0.f, l1 = 0.f;
    float o[4][4];
    #pragma unroll
    for (int n = 0; n < 4; n++)
        o[n][0] = o[n][1] = o[n][2] = o[n][3] = 0.f;

    const int ktBegin = z * KT_PER_SPLIT;
    for (int kt = ktBegin; kt < ktBegin + KT_PER_SPLIT; kt++) {
        if (kt != ktBegin) __syncthreads();
        // ---- load + split K,V tile ----
        for (int idx = tid; idx < 512; idx += 128) {
            int key = idx >> 3, dg = (idx & 7) << 2;
            int grow = ((kt * 64 + key) * B_SZ + b) * E_DIM + h * HD + dg;
            float4 kv = *(const float4*)&g_K[grow];
            float4 vv = *(const float4*)&g_V[grow];
            float4 khf, klf, vhf, vlf;
            split2(kv.x, khf.x, klf.x); split2(kv.y, khf.y, klf.y);
            split2(kv.z, khf.z, klf.z); split2(kv.w, khf.w, klf.w);
            split2(vv.x, vhf.x, vlf.x); split2(vv.y, vhf.y, vlf.y);
            split2(vv.z, vhf.z, vlf.z); split2(vv.w, vhf.w, vlf.w);
            *(float4*)&Khi[key * K_PITCH + dg] = khf;
            *(float4*)&Klo[key * K_PITCH + dg] = klf;
            *(float4*)&Vhi[key * V_PITCH + dg] = vhf;
            *(float4*)&Vlo[key * V_PITCH + dg] = vlf;
        }
        __syncthreads();

        // ---- S = Q K^T (3xTF32) ----
        float s[8][4];
        #pragma unroll
        for (int j = 0; j < 8; j++)
            s[j][0] = s[j][1] = s[j][2] = s[j][3] = 0.f;
        #pragma unroll
        for (int kk = 0; kk < 4; kk++) {
            #pragma unroll
            for (int j = 0; j < 8; j++) {
                int krow = (j * 8 + g) * K_PITCH;
                int c = kk * 8 + t4;
                uint32_t kb0 = __float_as_uint(Khi[krow + c]);
                uint32_t kb1 = __float_as_uint(Khi[krow + c + 4]);
                uint32_t lb0 = __float_as_uint(Klo[krow + c]);
                uint32_t lb1 = __float_as_uint(Klo[krow + c + 4]);
                mma8(s[j], qh[kk], kb0, kb1);
                mma8(s[j], ql[kk], kb0, kb1);
                mma8(s[j], qh[kk], lb0, lb1);
            }
        }

        // ---- online softmax ----
        float mx0 = -1e30f, mx1 = -1e30f;
        #pragma unroll
        for (int j = 0; j < 8; j++) {
            mx0 = fmaxf(mx0, fmaxf(s[j][0], s[j][1]));
            mx1 = fmaxf(mx1, fmaxf(s[j][2], s[j][3]));
        }
        mx0 = fmaxf(mx0, __shfl_xor_sync(0xffffffffu, mx0, 1));
        mx0 = fmaxf(mx0, __shfl_xor_sync(0xffffffffu, mx0, 2));
        mx1 = fmaxf(mx1, __shfl_xor_sync(0xffffffffu, mx1, 1));
        mx1 = fmaxf(mx1, __shfl_xor_sync(0xffffffffu, mx1, 2));
        float mn0 = fmaxf(m0, mx0), mn1 = fmaxf(m1, mx1);
        float al0 = __expf(m0 - mn0), al1 = __expf(m1 - mn1);
        float sum0 = 0.f, sum1 = 0.f;
        #pragma unroll
        for (int j = 0; j < 8; j++) {
            s[j][0] = __expf(s[j][0] - mn0);
            s[j][1] = __expf(s[j][1] - mn0);
            sum0 += s[j][0] + s[j][1];
            s[j][2] = __expf(s[j][2] - mn1);
            s[j][3] = __expf(s[j][3] - mn1);
            sum1 += s[j][2] + s[j][3];
        }
        sum0 += __shfl_xor_sync(0xffffffffu, sum0, 1);
        sum0 += __shfl_xor_sync(0xffffffffu, sum0, 2);
        sum1 += __shfl_xor_sync(0xffffffffu, sum1, 1);
        sum1 += __shfl_xor_sync(0xffffffffu, sum1, 2);
        l0 = l0 * al0 + sum0; m0 = mn0;
        l1 = l1 * al1 + sum1; m1 = mn1;
        #pragma unroll
        for (int n = 0; n < 4; n++) {
            o[n][0] *= al0; o[n][1] *= al0;
            o[n][2] *= al1; o[n][3] *= al1;
        }

        // ---- O += P V : C-frag -> A-frag via intra-quad shuffles ----
        #pragma unroll
        for (int ks = 0; ks < 8; ks++) {
            const int hsrc  = (lane & 28) + (t4 >> 1);
            const int hsrc2 = hsrc + 2;
            const bool odd = (t4 & 1);
            float b0 = __shfl_sync(0xffffffffu, s[ks][0], hsrc);
            float b1 = __shfl_sync(0xffffffffu, s[ks][1], hsrc);
            float c0 = __shfl_sync(0xffffffffu, s[ks][2], hsrc);
            float c1 = __shfl_sync(0xffffffffu, s[ks][3], hsrc);
            float d0 = __shfl_sync(0xffffffffu, s[ks][0], hsrc2);
            float d1 = __shfl_sync(0xffffffffu, s[ks][1], hsrc2);
            float e0 = __shfl_sync(0xffffffffu, s[ks][2], hsrc2);
            float e1 = __shfl_sync(0xffffffffu, s[ks][3], hsrc2);
            uint32_t pa[4];
            pa[0] = f2tf(odd ? b1 : b0);
            pa[1] = f2tf(odd ? c1 : c0);
            pa[2] = f2tf(odd ? d1 : d0);
            pa[3] = f2tf(odd ? e1 : e0);

            int vr0 = (ks * 8 + t4) * V_PITCH;
            int vr1 = (ks * 8 + t4 + 4) * V_PITCH;
            uint32_t vb0[4], vb1[4], wb0[4], wb1[4];
            #pragma unroll
            for (int n = 0; n < 4; n++) {
                int d0i = n * 8 + g;
                vb0[n] = __float_as_uint(Vhi[vr0 + d0i]);
                vb1[n] = __float_as_uint(Vhi[vr1 + d0i]);
                wb0[n] = __float_as_uint(Vlo[vr0 + d0i]);
                wb1[n] = __float_as_uint(Vlo[vr1 + d0i]);
            }
            #pragma unroll
            for (int n = 0; n < 4; n++)
                mma8(o[n], pa, vb0[n], vb1[n]);
            #pragma unroll
            for (int n = 0; n < 4; n++)
                mma8(o[n], pa, wb0[n], wb1[n]);
        }
    }

    // ---- epilogue: write unnormalized partials ----
    const int pbase = (z * NH * B_SZ + bh) * L_SEQ;   // row base for this split
    int qr0 = qBase + q0 + g;       // global q index
    int qr1 = qr0 + 8;
    #pragma unroll
    for (int n = 0; n < 4; n++) {
        int col = n * 8 + 2 * t4;
        *(float2*)&g_Po[(pbase + qr0) * HD + col] = make_float2(o[n][0], o[n][1]);
        *(float2*)&g_Po[(pbase + qr1) * HD + col] = make_float2(o[n][2], o[n][3]);
    }
    if (t4 == 0) {
        g_Pm[pbase + qr0] = m0;  g_Pl[pbase + qr0] = l0;
        g_Pm[pbase + qr1] = m1;  g_Pl[pbase + qr1] = l1;
    }
}

// ---------------------------------------------------------------------------
// Merge the NSPLIT partials: exact log-sum-exp combine, write g_O.
// 256 threads: 8 threads per (bh,q) row (4 dims each), 32 rows per block.
// Grid: BHL/32 = 1024.
// ---------------------------------------------------------------------------
__global__ __launch_bounds__(256) void attn_merge_kernel()
{
    const int tid = threadIdx.x;
    const int row = blockIdx.x * 32 + (tid >> 3);   // (bh, q) flat index
    const int d   = (tid & 7) * 4;

    const int bh = row >> 11;          // row / 2048
    const int q  = row & 2047;
    const int b  = bh >> 3;
    const int h  = bh & 7;

    float m0 = g_Pm[row], l0 = g_Pl[row];
    float m1 = g_Pm[BHL + row], l1 = g_Pl[BHL + row];
    float ms = fmaxf(m0, m1);
    float w0 = __expf(m0 - ms), w1 = __expf(m1 - ms);
    float inv = 1.0f / (l0 * w0 + l1 * w1);
    w0 *= inv; w1 *= inv;

    float4 p0 = *(const float4*)&g_Po[row * HD + d];
    float4 p1 = *(const float4*)&g_Po[(BHL + row) * HD + d];
    float4 r;
    r.x = p0.x * w0 + p1.x * w1;
    r.y = p0.y * w0 + p1.y * w1;
    r.z = p0.z * w0 + p1.z * w1;
    r.w = p0.w * w0 + p1.w * w1;
    *(float4*)&g_O[(q * B_SZ + b) * E_DIM + h * HD + d] = r;
}

// ---------------------------------------------------------------------------
extern "C" void kernel_launch(void* const* d_in, const int* in_sizes, int n_in,
                              void* d_out, int out_size)
{
    const float* query = (const float*)d_in[0];
    const float* key_  = (const float*)d_in[1];
    const float* value = (const float*)d_in[2];
    const float* Wq = (const float*)d_in[3];
    const float* bq = (const float*)d_in[4];
    const float* Wk = (const float*)d_in[5];
    const float* bk = (const float*)d_in[6];
    const float* Wv = (const float*)d_in[7];
    const float* bv = (const float*)d_in[8];
    const float* Wp = (const float*)d_in[9];
    const float* bp = (const float*)d_in[10];
    float* out = (float*)d_out;

    float *qbuf, *kbuf, *vbuf, *obuf;
    cudaGetSymbolAddress((void**)&qbuf, g_Q);
    cudaGetSymbolAddress((void**)&kbuf, g_K);
    cudaGetSymbolAddress((void**)&vbuf, g_V);
    cudaGetSymbolAddress((void**)&obuf, g_O);

    dim3 gg(E_DIM / 64, M_ROWS / 64);   // (4, 64)
    gemm_bias_kernel<<<gg, 256>>>(query, Wq, bq, qbuf);
    gemm_bias_kernel<<<gg, 256>>>(key_,  Wk, bk, kbuf);
    gemm_bias_kernel<<<gg, 256>>>(value, Wv, bv, vbuf);
    attn_tf32_kernel<<<dim3(L_SEQ / 64, B_SZ * NH, NSPLIT), 128>>>();
    attn_merge_kernel<<<BHL / 32, 256>>>();
    gemm_bias_kernel<<<gg, 256>>>(obuf, Wp, bp, out);
}

// round 8
// speedup vs baseline: 1.3603x; 1.2000x over previous
#include <cuda_runtime.h>
#include <math.h>
#include <stdint.h>

#define L_SEQ 2048
#define B_SZ 2
#define E_DIM 256
#define NH 8
#define HD 32
#define M_ROWS (L_SEQ * B_SZ)   // 4096
#define NSPLIT 2
#define BHL (NH * B_SZ * L_SEQ) // 32768

// Scratch (allocation-free rule: __device__ globals)
static __device__ float g_Q[M_ROWS * E_DIM];
static __device__ float g_K[M_ROWS * E_DIM];
static __device__ float g_V[M_ROWS * E_DIM];
static __device__ float g_O[M_ROWS * E_DIM];
static __device__ float g_Po[NSPLIT * BHL * HD];
static __device__ float g_Pm[NSPLIT * BHL];
static __device__ float g_Pl[NSPLIT * BHL];

// ---------------------------------------------------------------------------
// helpers: bf16 pack (truncation) / unpack / m16n8k16 bf16 mma
// ---------------------------------------------------------------------------
__device__ __forceinline__ uint32_t pk(float lo_e, float hi_e) {
    // low half <- bf16(lo_e), high half <- bf16(hi_e), by truncation
    return (__float_as_uint(hi_e) & 0xFFFF0000u) | (__float_as_uint(lo_e) >> 16);
}
__device__ __forceinline__ float lowf(uint32_t w)  { return __uint_as_float(w << 16); }
__device__ __forceinline__ float highf(uint32_t w) { return __uint_as_float(w & 0xFFFF0000u); }

__device__ __forceinline__ void mma16(float c[4], const uint32_t a[4],
                                      uint32_t b0, uint32_t b1) {
    asm("mma.sync.aligned.m16n8k16.row.col.f32.bf16.bf16.f32 "
        "{%0,%1,%2,%3}, {%4,%5,%6,%7}, {%8,%9}, {%0,%1,%2,%3};"
        : "+f"(c[0]), "+f"(c[1]), "+f"(c[2]), "+f"(c[3])
        : "r"(a[0]), "r"(a[1]), "r"(a[2]), "r"(a[3]), "r"(b0), "r"(b1));
}

// ---------------------------------------------------------------------------
// GEMM: out[M,N] = X[M,256] @ W[256,N] + bias[N]  (fp32 SIMT, proven)
// ---------------------------------------------------------------------------
__global__ __launch_bounds__(256) void gemm_bias_kernel(
    const float* __restrict__ X, const float* __restrict__ W,
    const float* __restrict__ bias, float* __restrict__ out)
{
    __shared__ float As[16][68];
    __shared__ float Bs[16][68];

    const int tid = threadIdx.x;
    const int tx  = tid & 15;
    const int ty  = tid >> 4;
    const int mBase = blockIdx.y * 64;
    const int nBase = blockIdx.x * 64;

    const int lr = tid >> 2;
    const int lk = (tid & 3) << 2;
    const int wr = tid >> 4;
    const int wn = (tid & 15) << 2;

    float c[4][4] = {};

    for (int k0 = 0; k0 < 256; k0 += 16) {
        float4 a = *(const float4*)&X[(mBase + lr) * 256 + k0 + lk];
        As[lk + 0][lr] = a.x; As[lk + 1][lr] = a.y;
        As[lk + 2][lr] = a.z; As[lk + 3][lr] = a.w;
        float4 bvec = *(const float4*)&W[(k0 + wr) * 256 + nBase + wn];
        *(float4*)&Bs[wr][wn] = bvec;
        __syncthreads();

        #pragma unroll
        for (int k = 0; k < 16; k++) {
            float4 av = *(float4*)&As[k][ty * 4];
            float4 bv = *(float4*)&Bs[k][tx * 4];
            float ar[4] = {av.x, av.y, av.z, av.w};
            float br[4] = {bv.x, bv.y, bv.z, bv.w};
            #pragma unroll
            for (int i = 0; i < 4; i++)
                #pragma unroll
                for (int j = 0; j < 4; j++)
                    c[i][j] += ar[i] * br[j];
        }
        __syncthreads();
    }

    float4 bb = *(const float4*)&bias[nBase + tx * 4];
    float bl[4] = {bb.x, bb.y, bb.z, bb.w};
    #pragma unroll
    for (int i = 0; i < 4; i++) {
        float4 o;
        o.x = c[i][0] + bl[0];
        o.y = c[i][1] + bl[1];
        o.z = c[i][2] + bl[2];
        o.w = c[i][3] + bl[3];
        *(float4*)&out[(mBase + ty * 4 + i) * 256 + nBase + tx * 4] = o;
    }
}

// ---------------------------------------------------------------------------
// Flash attention via bf16 m16n8k16 3-term splits, split-K over blockIdx.z.
// CTA: 128 threads (4 warps), BQ=64 (warp owns 16 q rows), BK=64.
// Grid (32, 16, 2). Each z covers 1024 keys, emits unnormalized partials.
//
// K smem KI[key][36]: words 0..15 = bf16x2 hi of d pairs (2j,2j+1),
//                     words 16..31 = lo pairs. pitch 36 -> banks 4g+t4 (CF).
// V smem VH/VL[kp][40]: kp = key pair; word d = pack(V[2kp][d], V[2kp+1][d]).
//                     pitch 40 -> banks 8t4+g (CF).
// PV A-fragment comes directly from S C-fragments (same lane): no shuffles.
// ---------------------------------------------------------------------------
#define KI_PITCH 36
#define V_PITCH 40
#define KT_PER_SPLIT (L_SEQ / 64 / NSPLIT)   // 16

__global__ __launch_bounds__(128, 4) void attn_bf16_kernel()
{
    __shared__ float KI[64 * KI_PITCH];
    __shared__ float VH[32 * V_PITCH];
    __shared__ float VL[32 * V_PITCH];

    const int tid  = threadIdx.x;
    const int warp = tid >> 5;
    const int lane = tid & 31;
    const int g    = lane >> 2;
    const int t4   = lane & 3;

    const int bh = blockIdx.y;
    const int z  = blockIdx.z;
    const int b  = bh >> 3;
    const int h  = bh & 7;
    const int qBase = blockIdx.x * 64;
    const int q0 = warp * 16;
    const float scale = 0.17677669529663687f;   // 32^-0.5

    // ---- Q A-fragments (one-time from gmem), scaled + hi/lo bf16 split ----
    uint32_t qh[2][4], ql[2][4];
    {
        const float* qr0 = &g_Q[((qBase + q0 + g) * B_SZ + b) * E_DIM + h * HD];
        const float* qr1 = qr0 + 8 * B_SZ * E_DIM;
        #pragma unroll
        for (int kk = 0; kk < 2; kk++) {
            int d0 = kk * 16 + 2 * t4;
            float v[8];
            v[0] = qr0[d0] * scale;     v[1] = qr0[d0 + 1] * scale;  // a0
            v[2] = qr1[d0] * scale;     v[3] = qr1[d0 + 1] * scale;  // a1
            v[4] = qr0[d0 + 8] * scale; v[5] = qr0[d0 + 9] * scale;  // a2
            v[6] = qr1[d0 + 8] * scale; v[7] = qr1[d0 + 9] * scale;  // a3
            #pragma unroll
            for (int r = 0; r < 4; r++) {
                uint32_t w = pk(v[2 * r], v[2 * r + 1]);
                qh[kk][r] = w;
                ql[kk][r] = pk(v[2 * r] - lowf(w), v[2 * r + 1] - highf(w));
            }
        }
    }

    float m0 = -1e30f, m1 = -1e30f, l0 = 0.f, l1 = 0.f;
    float o[4][4];
    #pragma unroll
    for (int n = 0; n < 4; n++)
        o[n][0] = o[n][1] = o[n][2] = o[n][3] = 0.f;

    const int ktBegin = z * KT_PER_SPLIT;
    for (int kt = ktBegin; kt < ktBegin + KT_PER_SPLIT; kt++) {
        if (kt != ktBegin) __syncthreads();

        // ---- load K tile: one (key, d16-chunk) per thread ----
        {
            int key = tid >> 1, kk = tid & 1;
            const float* src =
                &g_K[((kt * 64 + key) * B_SZ + b) * E_DIM + h * HD + kk * 16];
            float4 x0 = *(const float4*)(src);
            float4 x1 = *(const float4*)(src + 4);
            float4 x2 = *(const float4*)(src + 8);
            float4 x3 = *(const float4*)(src + 12);
            float v[16] = {x0.x, x0.y, x0.z, x0.w, x1.x, x1.y, x1.z, x1.w,
                           x2.x, x2.y, x2.z, x2.w, x3.x, x3.y, x3.z, x3.w};
            uint32_t hi[8], lo[8];
            #pragma unroll
            for (int i = 0; i < 8; i++) {
                uint32_t w = pk(v[2 * i], v[2 * i + 1]);
                hi[i] = w;
                lo[i] = pk(v[2 * i] - lowf(w), v[2 * i + 1] - highf(w));
            }
            float* dst = &KI[key * KI_PITCH + kk * 8];
            *(float4*)(dst)      = *(float4*)(hi);
            *(float4*)(dst + 4)  = *(float4*)(hi + 4);
            *(float4*)(dst + 16) = *(float4*)(lo);
            *(float4*)(dst + 20) = *(float4*)(lo + 4);
        }
        // ---- load V tile: one (key-pair, dim-octet) per thread ----
        {
            int kp = tid >> 2, dg = (tid & 3) * 8;
            const float* s0 =
                &g_V[((kt * 64 + 2 * kp) * B_SZ + b) * E_DIM + h * HD + dg];
            const float* s1 = s0 + B_SZ * E_DIM;
            float4 a0 = *(const float4*)(s0);
            float4 a1 = *(const float4*)(s0 + 4);
            float4 c0 = *(const float4*)(s1);
            float4 c1 = *(const float4*)(s1 + 4);
            float va[8] = {a0.x, a0.y, a0.z, a0.w, a1.x, a1.y, a1.z, a1.w};
            float vb[8] = {c0.x, c0.y, c0.z, c0.w, c1.x, c1.y, c1.z, c1.w};
            uint32_t hi[8], lo[8];
            #pragma unroll
            for (int i = 0; i < 8; i++) {
                uint32_t w = pk(va[i], vb[i]);   // low half = even key
                hi[i] = w;
                lo[i] = pk(va[i] - lowf(w), vb[i] - highf(w));
            }
            *(float4*)&VH[kp * V_PITCH + dg]     = *(float4*)(hi);
            *(float4*)&VH[kp * V_PITCH + dg + 4] = *(float4*)(hi + 4);
            *(float4*)&VL[kp * V_PITCH + dg]     = *(float4*)(lo);
            *(float4*)&VL[kp * V_PITCH + dg + 4] = *(float4*)(lo + 4);
        }
        __syncthreads();

        // ---- S = Q K^T (3x bf16 k16) ----
        float s[8][4];
        #pragma unroll
        for (int j = 0; j < 8; j++)
            s[j][0] = s[j][1] = s[j][2] = s[j][3] = 0.f;
        #pragma unroll
        for (int kk = 0; kk < 2; kk++) {
            #pragma unroll
            for (int j = 0; j < 8; j++) {
                int base = (j * 8 + g) * KI_PITCH + kk * 8;
                uint32_t kb0h = __float_as_uint(KI[base + t4]);
                uint32_t kb1h = __float_as_uint(KI[base + 4 + t4]);
                uint32_t kb0l = __float_as_uint(KI[base + 16 + t4]);
                uint32_t kb1l = __float_as_uint(KI[base + 20 + t4]);
                mma16(s[j], qh[kk], kb0h, kb1h);
                mma16(s[j], ql[kk], kb0h, kb1h);
                mma16(s[j], qh[kk], kb0l, kb1l);
            }
        }

        // ---- online softmax ----
        float mx0 = -1e30f, mx1 = -1e30f;
        #pragma unroll
        for (int j = 0; j < 8; j++) {
            mx0 = fmaxf(mx0, fmaxf(s[j][0], s[j][1]));
            mx1 = fmaxf(mx1, fmaxf(s[j][2], s[j][3]));
        }
        mx0 = fmaxf(mx0, __shfl_xor_sync(0xffffffffu, mx0, 1));
        mx0 = fmaxf(mx0, __shfl_xor_sync(0xffffffffu, mx0, 2));
        mx1 = fmaxf(mx1, __shfl_xor_sync(0xffffffffu, mx1, 1));
        mx1 = fmaxf(mx1, __shfl_xor_sync(0xffffffffu, mx1, 2));
        float mn0 = fmaxf(m0, mx0), mn1 = fmaxf(m1, mx1);
        float al0 = __expf(m0 - mn0), al1 = __expf(m1 - mn1);
        float sum0 = 0.f, sum1 = 0.f;
        #pragma unroll
        for (int j = 0; j < 8; j++) {
            s[j][0] = __expf(s[j][0] - mn0);
            s[j][1] = __expf(s[j][1] - mn0);
            sum0 += s[j][0] + s[j][1];
            s[j][2] = __expf(s[j][2] - mn1);
            s[j][3] = __expf(s[j][3] - mn1);
            sum1 += s[j][2] + s[j][3];
        }
        sum0 += __shfl_xor_sync(0xffffffffu, sum0, 1);
        sum0 += __shfl_xor_sync(0xffffffffu, sum0, 2);
        sum1 += __shfl_xor_sync(0xffffffffu, sum1, 1);
        sum1 += __shfl_xor_sync(0xffffffffu, sum1, 2);
        l0 = l0 * al0 + sum0; m0 = mn0;
        l1 = l1 * al1 + sum1; m1 = mn1;
        #pragma unroll
        for (int n = 0; n < 4; n++) {
            o[n][0] *= al0; o[n][1] *= al0;
            o[n][2] *= al1; o[n][3] *= al1;
        }

        // ---- O += P V : A-frag = stacked C-frags, in-lane ----
        #pragma unroll
        for (int kb = 0; kb < 4; kb++) {
            uint32_t pa[4], pl[4];
            {
                float x0 = s[2 * kb][0],     x1 = s[2 * kb][1];
                float y0 = s[2 * kb][2],     y1 = s[2 * kb][3];
                float z0 = s[2 * kb + 1][0], z1 = s[2 * kb + 1][1];
                float w0 = s[2 * kb + 1][2], w1 = s[2 * kb + 1][3];
                pa[0] = pk(x0, x1); pl[0] = pk(x0 - lowf(pa[0]), x1 - highf(pa[0]));
                pa[1] = pk(y0, y1); pl[1] = pk(y0 - lowf(pa[1]), y1 - highf(pa[1]));
                pa[2] = pk(z0, z1); pl[2] = pk(z0 - lowf(pa[2]), z1 - highf(pa[2]));
                pa[3] = pk(w0, w1); pl[3] = pk(w0 - lowf(pa[3]), w1 - highf(pa[3]));
            }
            int r0 = (kb * 8 + t4) * V_PITCH;
            int r1 = (kb * 8 + 4 + t4) * V_PITCH;
            #pragma unroll
            for (int n = 0; n < 4; n++) {
                int dc = n * 8 + g;
                uint32_t vb0h = __float_as_uint(VH[r0 + dc]);
                uint32_t vb1h = __float_as_uint(VH[r1 + dc]);
                uint32_t vb0l = __float_as_uint(VL[r0 + dc]);
                uint32_t vb1l = __float_as_uint(VL[r1 + dc]);
                mma16(o[n], pa, vb0h, vb1h);
                mma16(o[n], pl, vb0h, vb1h);
                mma16(o[n], pa, vb0l, vb1l);
            }
        }
    }

    // ---- epilogue: write unnormalized partials ----
    const int pbase = (z * NH * B_SZ + bh) * L_SEQ;
    int qr0 = qBase + q0 + g;
    int qr1 = qr0 + 8;
    #pragma unroll
    for (int n = 0; n < 4; n++) {
        int col = n * 8 + 2 * t4;
        *(float2*)&g_Po[(pbase + qr0) * HD + col] = make_float2(o[n][0], o[n][1]);
        *(float2*)&g_Po[(pbase + qr1) * HD + col] = make_float2(o[n][2], o[n][3]);
    }
    if (t4 == 0) {
        g_Pm[pbase + qr0] = m0;  g_Pl[pbase + qr0] = l0;
        g_Pm[pbase + qr1] = m1;  g_Pl[pbase + qr1] = l1;
    }
}

// ---------------------------------------------------------------------------
// Merge the NSPLIT partials (exact log-sum-exp), write g_O.
// ---------------------------------------------------------------------------
__global__ __launch_bounds__(256) void attn_merge_kernel()
{
    const int tid = threadIdx.x;
    const int row = blockIdx.x * 32 + (tid >> 3);
    const int d   = (tid & 7) * 4;

    const int bh = row >> 11;
    const int q  = row & 2047;
    const int b  = bh >> 3;
    const int h  = bh & 7;

    float m0 = g_Pm[row], l0 = g_Pl[row];
    float m1 = g_Pm[BHL + row], l1 = g_Pl[BHL + row];
    float ms = fmaxf(m0, m1);
    float w0 = __expf(m0 - ms), w1 = __expf(m1 - ms);
    float inv = 1.0f / (l0 * w0 + l1 * w1);
    w0 *= inv; w1 *= inv;

    float4 p0 = *(const float4*)&g_Po[row * HD + d];
    float4 p1 = *(const float4*)&g_Po[(BHL + row) * HD + d];
    float4 r;
    r.x = p0.x * w0 + p1.x * w1;
    r.y = p0.y * w0 + p1.y * w1;
    r.z = p0.z * w0 + p1.z * w1;
    r.w = p0.w * w0 + p1.w * w1;
    *(float4*)&g_O[(q * B_SZ + b) * E_DIM + h * HD + d] = r;
}

// ---------------------------------------------------------------------------
extern "C" void kernel_launch(void* const* d_in, const int* in_sizes, int n_in,
                              void* d_out, int out_size)
{
    const float* query = (const float*)d_in[0];
    const float* key_  = (const float*)d_in[1];
    const float* value = (const float*)d_in[2];
    const float* Wq = (const float*)d_in[3];
    const float* bq = (const float*)d_in[4];
    const float* Wk = (const float*)d_in[5];
    const float* bk = (const float*)d_in[6];
    const float* Wv = (const float*)d_in[7];
    const float* bv = (const float*)d_in[8];
    const float* Wp = (const float*)d_in[9];
    const float* bp = (const float*)d_in[10];
    float* out = (float*)d_out;

    float *qbuf, *kbuf, *vbuf, *obuf;
    cudaGetSymbolAddress((void**)&qbuf, g_Q);
    cudaGetSymbolAddress((void**)&kbuf, g_K);
    cudaGetSymbolAddress((void**)&vbuf, g_V);
    cudaGetSymbolAddress((void**)&obuf, g_O);

    dim3 gg(E_DIM / 64, M_ROWS / 64);   // (4, 64)
    gemm_bias_kernel<<<gg, 256>>>(query, Wq, bq, qbuf);
    gemm_bias_kernel<<<gg, 256>>>(key_,  Wk, bk, kbuf);
    gemm_bias_kernel<<<gg, 256>>>(value, Wv, bv, vbuf);
    attn_bf16_kernel<<<dim3(L_SEQ / 64, B_SZ * NH, NSPLIT), 128>>>();
    attn_merge_kernel<<<BHL / 32, 256>>>();
    gemm_bias_kernel<<<gg, 256>>>(obuf, Wp, bp, out);
}

// round 9
// speedup vs baseline: 1.3757x; 1.0113x over previous
#include <cuda_runtime.h>
#include <math.h>
#include <stdint.h>

#define L_SEQ 2048
#define B_SZ 2
#define E_DIM 256
#define NH 8
#define HD 32
#define M_ROWS (L_SEQ * B_SZ)   // 4096
#define NSPLIT 2
#define BHL (NH * B_SZ * L_SEQ) // 32768

// Scratch (allocation-free rule: __device__ globals)
// Packed bf16 hi/lo tensors, laid out per (bh) exactly as attention smem wants:
//  g_QP/g_KP[bh][q|key][32]: word p (0..15) = bf16x2(dim 2p, dim 2p+1) hi,
//                            word 16+p = lo residual pair. (Q pre-scaled.)
//  g_VP[bh][kp][64]: word d (0..31) = bf16x2(V[2kp][d], V[2kp+1][d]) hi,
//                    word 32+d = lo residual.
static __device__ float g_QP[16 * 2048 * 32];
static __device__ float g_KP[16 * 2048 * 32];
static __device__ float g_VP[16 * 1024 * 64];
static __device__ float g_O[M_ROWS * E_DIM];
static __device__ float g_Po[NSPLIT * BHL * HD];
static __device__ float g_Pm[NSPLIT * BHL];
static __device__ float g_Pl[NSPLIT * BHL];

// ---------------------------------------------------------------------------
// helpers
// ---------------------------------------------------------------------------
__device__ __forceinline__ uint32_t pk(float lo_e, float hi_e) {
    return (__float_as_uint(hi_e) & 0xFFFF0000u) | (__float_as_uint(lo_e) >> 16);
}
__device__ __forceinline__ float lowf(uint32_t w)  { return __uint_as_float(w << 16); }
__device__ __forceinline__ float highf(uint32_t w) { return __uint_as_float(w & 0xFFFF0000u); }

__device__ __forceinline__ void mma16(float c[4], const uint32_t a[4],
                                      uint32_t b0, uint32_t b1) {
    asm("mma.sync.aligned.m16n8k16.row.col.f32.bf16.bf16.f32 "
        "{%0,%1,%2,%3}, {%4,%5,%6,%7}, {%8,%9}, {%0,%1,%2,%3};"
        : "+f"(c[0]), "+f"(c[1]), "+f"(c[2]), "+f"(c[3])
        : "r"(a[0]), "r"(a[1]), "r"(a[2]), "r"(a[3]), "r"(b0), "r"(b1));
}

// ---------------------------------------------------------------------------
// Shared fp32 SIMT GEMM mainloop (proven). Epilogue varies per variant.
// ---------------------------------------------------------------------------
#define GEMM_PROLOG_AND_MAINLOOP \
    __shared__ float As[16][68];                                          \
    __shared__ float Bs[16][68];                                          \
    const int tid = threadIdx.x;                                          \
    const int tx  = tid & 15;                                             \
    const int ty  = tid >> 4;                                             \
    const int mBase = blockIdx.y * 64;                                    \
    const int nBase = blockIdx.x * 64;                                    \
    const int lr = tid >> 2;                                              \
    const int lk = (tid & 3) << 2;                                        \
    const int wr = tid >> 4;                                              \
    const int wn = (tid & 15) << 2;                                       \
    float c[4][4] = {};                                                   \
    for (int k0 = 0; k0 < 256; k0 += 16) {                                \
        float4 a = *(const float4*)&X[(mBase + lr) * 256 + k0 + lk];      \
        As[lk + 0][lr] = a.x; As[lk + 1][lr] = a.y;                       \
        As[lk + 2][lr] = a.z; As[lk + 3][lr] = a.w;                       \
        float4 bvec = *(const float4*)&W[(k0 + wr) * 256 + nBase + wn];   \
        *(float4*)&Bs[wr][wn] = bvec;                                     \
        __syncthreads();                                                  \
        _Pragma("unroll")                                                 \
        for (int k = 0; k < 16; k++) {                                    \
            float4 av = *(float4*)&As[k][ty * 4];                         \
            float4 bv = *(float4*)&Bs[k][tx * 4];                         \
            float ar[4] = {av.x, av.y, av.z, av.w};                       \
            float br[4] = {bv.x, bv.y, bv.z, bv.w};                       \
            _Pragma("unroll")                                             \
            for (int i = 0; i < 4; i++)                                   \
                _Pragma("unroll")                                         \
                for (int j = 0; j < 4; j++)                               \
                    c[i][j] += ar[i] * br[j];                             \
        }                                                                 \
        __syncthreads();                                                  \
    }

// Output projection: plain fp32 + bias
__global__ __launch_bounds__(256) void gemm_bias_kernel(
    const float* __restrict__ X, const float* __restrict__ W,
    const float* __restrict__ bias, float* __restrict__ out)
{
    GEMM_PROLOG_AND_MAINLOOP
    float4 bb = *(const float4*)&bias[nBase + tx * 4];
    float bl[4] = {bb.x, bb.y, bb.z, bb.w};
    #pragma unroll
    for (int i = 0; i < 4; i++) {
        float4 o;
        o.x = c[i][0] + bl[0];
        o.y = c[i][1] + bl[1];
        o.z = c[i][2] + bl[2];
        o.w = c[i][3] + bl[3];
        *(float4*)&out[(mBase + ty * 4 + i) * 256 + nBase + tx * 4] = o;
    }
}

// Q/K projection: write packed dim-pair hi/lo layout (Q pre-scaled)
__global__ __launch_bounds__(256) void gemm_pack_pairs_kernel(
    const float* __restrict__ X, const float* __restrict__ W,
    const float* __restrict__ bias, float* __restrict__ outP, float scale)
{
    GEMM_PROLOG_AND_MAINLOOP
    float4 bb = *(const float4*)&bias[nBase + tx * 4];
    float bl[4] = {bb.x, bb.y, bb.z, bb.w};
    const int col0 = nBase + tx * 4;
    const int h  = col0 >> 5;
    const int p0 = (col0 & 31) >> 1;
    #pragma unroll
    for (int i = 0; i < 4; i++) {
        int row = mBase + ty * 4 + i;
        int q = row >> 1, b = row & 1;
        float v0 = (c[i][0] + bl[0]) * scale;
        float v1 = (c[i][1] + bl[1]) * scale;
        float v2 = (c[i][2] + bl[2]) * scale;
        float v3 = (c[i][3] + bl[3]) * scale;
        uint32_t h0 = pk(v0, v1), h1 = pk(v2, v3);
        uint32_t e0 = pk(v0 - lowf(h0), v1 - highf(h0));
        uint32_t e1 = pk(v2 - lowf(h1), v3 - highf(h1));
        float* dst = &outP[((((b << 3) + h) << 11) + q) * 32];
        *(float2*)&dst[p0]      = make_float2(__uint_as_float(h0), __uint_as_float(h1));
        *(float2*)&dst[16 + p0] = make_float2(__uint_as_float(e0), __uint_as_float(e1));
    }
}

// V projection: write key-pair-packed hi/lo layout
__global__ __launch_bounds__(256) void gemm_pack_vkeys_kernel(
    const float* __restrict__ X, const float* __restrict__ W,
    const float* __restrict__ bias, float* __restrict__ outP)
{
    GEMM_PROLOG_AND_MAINLOOP
    float4 bb = *(const float4*)&bias[nBase + tx * 4];
    float bl[4] = {bb.x, bb.y, bb.z, bb.w};
    const int col0 = nBase + tx * 4;
    const int h  = col0 >> 5;
    const int d0 = col0 & 31;
    const int L0 = (mBase + ty * 4) >> 1;  // even; keys L0, L0+1
    const int kp = L0 >> 1;
    // rows: i=0 -> (key L0, b0), i=1 -> (L0, b1), i=2 -> (L0+1, b0), i=3 -> (L0+1, b1)
    #pragma unroll
    for (int b = 0; b < 2; b++) {
        uint32_t hw[4], lw[4];
        #pragma unroll
        for (int j = 0; j < 4; j++) {
            float a = c[b][j] + bl[j];        // key L0
            float d = c[2 + b][j] + bl[j];    // key L0+1
            hw[j] = pk(a, d);
            lw[j] = pk(a - lowf(hw[j]), d - highf(hw[j]));
        }
        float* dst = &outP[((((b << 3) + h) << 10) + kp) * 64];
        *(float4*)&dst[d0]      = *(float4*)hw;
        *(float4*)&dst[32 + d0] = *(float4*)lw;
    }
}

// ---------------------------------------------------------------------------
// Flash attention, bf16 m16n8k16 3-term, split-K. Loads PRE-PACKED tensors:
// tile load is a pure LDG.128->STS.128 copy (no conversion ALU).
// CTA: 128 threads (4 warps), BQ=64, BK=64. Grid (32, 16, 2).
// smem: KI[64][36] (words 0..15 hi, 16..31 lo), VH/VL[32][40] (+4 pad between
// for conflict-free copy). All compute reads bank-conflict-free.
// ---------------------------------------------------------------------------
#define KI_PITCH 36
#define V_PITCH 40
#define KT_PER_SPLIT (L_SEQ / 64 / NSPLIT)   // 16
#define SM_KI 0
#define SM_VH (64 * KI_PITCH)
#define SM_VL (SM_VH + 32 * V_PITCH + 4)
#define SM_TOT (SM_VL + 32 * V_PITCH)

__global__ __launch_bounds__(128, 4) void attn_bf16_kernel()
{
    __shared__ float SM[SM_TOT];
    float* KI = SM + SM_KI;
    float* VH = SM + SM_VH;
    float* VL = SM + SM_VL;

    const int tid  = threadIdx.x;
    const int warp = tid >> 5;
    const int lane = tid & 31;
    const int g    = lane >> 2;
    const int t4   = lane & 3;

    const int bh = blockIdx.y;
    const int z  = blockIdx.z;
    const int qBase = blockIdx.x * 64;
    const int q0 = warp * 16;

    // ---- Q A-fragments from pre-packed gmem ----
    uint32_t qh[2][4], ql[2][4];
    {
        const int base0 = ((bh << 11) + qBase + q0 + g) * 32;
        const int base1 = base0 + 8 * 32;
        #pragma unroll
        for (int kk = 0; kk < 2; kk++) {
            int p = kk * 8 + t4;
            qh[kk][0] = __float_as_uint(g_QP[base0 + p]);
            qh[kk][1] = __float_as_uint(g_QP[base1 + p]);
            qh[kk][2] = __float_as_uint(g_QP[base0 + p + 4]);
            qh[kk][3] = __float_as_uint(g_QP[base1 + p + 4]);
            ql[kk][0] = __float_as_uint(g_QP[base0 + 16 + p]);
            ql[kk][1] = __float_as_uint(g_QP[base1 + 16 + p]);
            ql[kk][2] = __float_as_uint(g_QP[base0 + 16 + p + 4]);
            ql[kk][3] = __float_as_uint(g_QP[base1 + 16 + p + 4]);
        }
    }

    float m0 = -1e30f, m1 = -1e30f, l0 = 0.f, l1 = 0.f;
    float o[4][4];
    #pragma unroll
    for (int n = 0; n < 4; n++)
        o[n][0] = o[n][1] = o[n][2] = o[n][3] = 0.f;

    const int ktBegin = z * KT_PER_SPLIT;
    for (int kt = ktBegin; kt < ktBegin + KT_PER_SPLIT; kt++) {
        if (kt != ktBegin) __syncthreads();

        // ---- K tile copy: 16 consecutive words per thread ----
        {
            int key = tid >> 1, half = (tid & 1) * 16;
            const float* src = &g_KP[(((bh << 11) + kt * 64 + key) << 5) + half];
            float* dst = &KI[key * KI_PITCH + half];
            float4 x0 = ((const float4*)src)[0];
            float4 x1 = ((const float4*)src)[1];
            float4 x2 = ((const float4*)src)[2];
            float4 x3 = ((const float4*)src)[3];
            *(float4*)(dst)      = x0;
            *(float4*)(dst + 4)  = x1;
            *(float4*)(dst + 8)  = x2;
            *(float4*)(dst + 12) = x3;
        }
        // ---- V tile copy ----
        {
            int kp = tid >> 2, quarter = tid & 3;
            const float* src = &g_VP[(((bh << 10) + kt * 32 + kp) << 6) + quarter * 16];
            float* dst = ((quarter < 2) ? VH : VL) + kp * V_PITCH + (quarter & 1) * 16;
            float4 x0 = ((const float4*)src)[0];
            float4 x1 = ((const float4*)src)[1];
            float4 x2 = ((const float4*)src)[2];
            float4 x3 = ((const float4*)src)[3];
            *(float4*)(dst)      = x0;
            *(float4*)(dst + 4)  = x1;
            *(float4*)(dst + 8)  = x2;
            *(float4*)(dst + 12) = x3;
        }
        __syncthreads();

        // ---- S = Q K^T (3x bf16 k16) ----
        float s[8][4];
        #pragma unroll
        for (int j = 0; j < 8; j++)
            s[j][0] = s[j][1] = s[j][2] = s[j][3] = 0.f;
        #pragma unroll
        for (int kk = 0; kk < 2; kk++) {
            #pragma unroll
            for (int j = 0; j < 8; j++) {
                int base = (j * 8 + g) * KI_PITCH + kk * 8;
                uint32_t kb0h = __float_as_uint(KI[base + t4]);
                uint32_t kb1h = __float_as_uint(KI[base + 4 + t4]);
                uint32_t kb0l = __float_as_uint(KI[base + 16 + t4]);
                uint32_t kb1l = __float_as_uint(KI[base + 20 + t4]);
                mma16(s[j], qh[kk], kb0h, kb1h);
                mma16(s[j], ql[kk], kb0h, kb1h);
                mma16(s[j], qh[kk], kb0l, kb1l);
            }
        }

        // ---- online softmax ----
        float mx0 = -1e30f, mx1 = -1e30f;
        #pragma unroll
        for (int j = 0; j < 8; j++) {
            mx0 = fmaxf(mx0, fmaxf(s[j][0], s[j][1]));
            mx1 = fmaxf(mx1, fmaxf(s[j][2], s[j][3]));
        }
        mx0 = fmaxf(mx0, __shfl_xor_sync(0xffffffffu, mx0, 1));
        mx0 = fmaxf(mx0, __shfl_xor_sync(0xffffffffu, mx0, 2));
        mx1 = fmaxf(mx1, __shfl_xor_sync(0xffffffffu, mx1, 1));
        mx1 = fmaxf(mx1, __shfl_xor_sync(0xffffffffu, mx1, 2));
        float mn0 = fmaxf(m0, mx0), mn1 = fmaxf(m1, mx1);
        float al0 = __expf(m0 - mn0), al1 = __expf(m1 - mn1);
        float sum0 = 0.f, sum1 = 0.f;
        #pragma unroll
        for (int j = 0; j < 8; j++) {
            s[j][0] = __expf(s[j][0] - mn0);
            s[j][1] = __expf(s[j][1] - mn0);
            sum0 += s[j][0] + s[j][1];
            s[j][2] = __expf(s[j][2] - mn1);
            s[j][3] = __expf(s[j][3] - mn1);
            sum1 += s[j][2] + s[j][3];
        }
        sum0 += __shfl_xor_sync(0xffffffffu, sum0, 1);
        sum0 += __shfl_xor_sync(0xffffffffu, sum0, 2);
        sum1 += __shfl_xor_sync(0xffffffffu, sum1, 1);
        sum1 += __shfl_xor_sync(0xffffffffu, sum1, 2);
        l0 = l0 * al0 + sum0; m0 = mn0;
        l1 = l1 * al1 + sum1; m1 = mn1;
        #pragma unroll
        for (int n = 0; n < 4; n++) {
            o[n][0] *= al0; o[n][1] *= al0;
            o[n][2] *= al1; o[n][3] *= al1;
        }

        // ---- O += P V : A-frag = stacked C-frags, in-lane ----
        #pragma unroll
        for (int kb = 0; kb < 4; kb++) {
            uint32_t pa[4], pl[4];
            {
                float x0 = s[2 * kb][0],     x1 = s[2 * kb][1];
                float y0 = s[2 * kb][2],     y1 = s[2 * kb][3];
                float z0 = s[2 * kb + 1][0], z1 = s[2 * kb + 1][1];
                float w0 = s[2 * kb + 1][2], w1 = s[2 * kb + 1][3];
                pa[0] = pk(x0, x1); pl[0] = pk(x0 - lowf(pa[0]), x1 - highf(pa[0]));
                pa[1] = pk(y0, y1); pl[1] = pk(y0 - lowf(pa[1]), y1 - highf(pa[1]));
                pa[2] = pk(z0, z1); pl[2] = pk(z0 - lowf(pa[2]), z1 - highf(pa[2]));
                pa[3] = pk(w0, w1); pl[3] = pk(w0 - lowf(pa[3]), w1 - highf(pa[3]));
            }
            int r0 = (kb * 8 + t4) * V_PITCH;
            int r1 = (kb * 8 + 4 + t4) * V_PITCH;
            #pragma unroll
            for (int n = 0; n < 4; n++) {
                int dc = n * 8 + g;
                uint32_t vb0h = __float_as_uint(VH[r0 + dc]);
                uint32_t vb1h = __float_as_uint(VH[r1 + dc]);
                uint32_t vb0l = __float_as_uint(VL[r0 + dc]);
                uint32_t vb1l = __float_as_uint(VL[r1 + dc]);
                mma16(o[n], pa, vb0h, vb1h);
                mma16(o[n], pl, vb0h, vb1h);
                mma16(o[n], pa, vb0l, vb1l);
            }
        }
    }

    // ---- epilogue: write unnormalized partials ----
    const int pbase = (z * NH * B_SZ + bh) * L_SEQ;
    int qr0 = qBase + q0 + g;
    int qr1 = qr0 + 8;
    #pragma unroll
    for (int n = 0; n < 4; n++) {
        int col = n * 8 + 2 * t4;
        *(float2*)&g_Po[(pbase + qr0) * HD + col] = make_float2(o[n][0], o[n][1]);
        *(float2*)&g_Po[(pbase + qr1) * HD + col] = make_float2(o[n][2], o[n][3]);
    }
    if (t4 == 0) {
        g_Pm[pbase + qr0] = m0;  g_Pl[pbase + qr0] = l0;
        g_Pm[pbase + qr1] = m1;  g_Pl[pbase + qr1] = l1;
    }
}

// ---------------------------------------------------------------------------
// Merge the NSPLIT partials (exact log-sum-exp), write g_O.
// ---------------------------------------------------------------------------
__global__ __launch_bounds__(256) void attn_merge_kernel()
{
    const int tid = threadIdx.x;
    const int row = blockIdx.x * 32 + (tid >> 3);
    const int d   = (tid & 7) * 4;

    const int bh = row >> 11;
    const int q  = row & 2047;
    const int b  = bh >> 3;
    const int h  = bh & 7;

    float m0 = g_Pm[row], l0 = g_Pl[row];
    float m1 = g_Pm[BHL + row], l1 = g_Pl[BHL + row];
    float ms = fmaxf(m0, m1);
    float w0 = __expf(m0 - ms), w1 = __expf(m1 - ms);
    float inv = 1.0f / (l0 * w0 + l1 * w1);
    w0 *= inv; w1 *= inv;

    float4 p0 = *(const float4*)&g_Po[row * HD + d];
    float4 p1 = *(const float4*)&g_Po[(BHL + row) * HD + d];
    float4 r;
    r.x = p0.x * w0 + p1.x * w1;
    r.y = p0.y * w0 + p1.y * w1;
    r.z = p0.z * w0 + p1.z * w1;
    r.w = p0.w * w0 + p1.w * w1;
    *(float4*)&g_O[(q * B_SZ + b) * E_DIM + h * HD + d] = r;
}

// ---------------------------------------------------------------------------
extern "C" void kernel_launch(void* const* d_in, const int* in_sizes, int n_in,
                              void* d_out, int out_size)
{
    const float* query = (const float*)d_in[0];
    const float* key_  = (const float*)d_in[1];
    const float* value = (const float*)d_in[2];
    const float* Wq = (const float*)d_in[3];
    const float* bq = (const float*)d_in[4];
    const float* Wk = (const float*)d_in[5];
    const float* bk = (const float*)d_in[6];
    const float* Wv = (const float*)d_in[7];
    const float* bv = (const float*)d_in[8];
    const float* Wp = (const float*)d_in[9];
    const float* bp = (const float*)d_in[10];
    float* out = (float*)d_out;

    float *qpbuf, *kpbuf, *vpbuf, *obuf;
    cudaGetSymbolAddress((void**)&qpbuf, g_QP);
    cudaGetSymbolAddress((void**)&kpbuf, g_KP);
    cudaGetSymbolAddress((void**)&vpbuf, g_VP);
    cudaGetSymbolAddress((void**)&obuf, g_O);

    const float scale = 0.17677669529663687f;   // 32^-0.5
    dim3 gg(E_DIM / 64, M_ROWS / 64);   // (4, 64)
    gemm_pack_pairs_kernel<<<gg, 256>>>(query, Wq, bq, qpbuf, scale);
    gemm_pack_pairs_kernel<<<gg, 256>>>(key_,  Wk, bk, kpbuf, 1.0f);
    gemm_pack_vkeys_kernel<<<gg, 256>>>(value, Wv, bv, vpbuf);
    attn_bf16_kernel<<<dim3(L_SEQ / 64, B_SZ * NH, NSPLIT), 128>>>();
    attn_merge_kernel<<<BHL / 32, 256>>>();
    gemm_bias_kernel<<<gg, 256>>>(obuf, Wp, bp, out);
}

// round 10
// speedup vs baseline: 1.3792x; 1.0025x over previous
#include <cuda_runtime.h>
#include <math.h>
#include <stdint.h>

#define L_SEQ 2048
#define B_SZ 2
#define E_DIM 256
#define NH 8
#define HD 32
#define M_ROWS (L_SEQ * B_SZ)   // 4096
#define NSPLIT 2
#define BHL (NH * B_SZ * L_SEQ) // 32768

// Packed bf16 hi/lo tensors (see round-9 layout comments)
static __device__ float g_QP[16 * 2048 * 32];
static __device__ float g_KP[16 * 2048 * 32];
static __device__ float g_VP[16 * 1024 * 64];
static __device__ float g_O[M_ROWS * E_DIM];
static __device__ float g_Po[NSPLIT * BHL * HD];
static __device__ float g_Pm[NSPLIT * BHL];
static __device__ float g_Pl[NSPLIT * BHL];

// ---------------------------------------------------------------------------
// helpers
// ---------------------------------------------------------------------------
__device__ __forceinline__ uint32_t pk(float lo_e, float hi_e) {
    return (__float_as_uint(hi_e) & 0xFFFF0000u) | (__float_as_uint(lo_e) >> 16);
}
__device__ __forceinline__ float lowf(uint32_t w)  { return __uint_as_float(w << 16); }
__device__ __forceinline__ float highf(uint32_t w) { return __uint_as_float(w & 0xFFFF0000u); }

__device__ __forceinline__ void mma16(float c[4], const uint32_t a[4],
                                      uint32_t b0, uint32_t b1) {
    asm("mma.sync.aligned.m16n8k16.row.col.f32.bf16.bf16.f32 "
        "{%0,%1,%2,%3}, {%4,%5,%6,%7}, {%8,%9}, {%0,%1,%2,%3};"
        : "+f"(c[0]), "+f"(c[1]), "+f"(c[2]), "+f"(c[3])
        : "r"(a[0]), "r"(a[1]), "r"(a[2]), "r"(a[3]), "r"(b0), "r"(b1));
}

__device__ __forceinline__ void cpa16(uint32_t dst_smem, const float* src) {
    asm volatile("cp.async.cg.shared.global [%0], [%1], 16;"
                 :: "r"(dst_smem), "l"(src));
}
#define CP_COMMIT() asm volatile("cp.async.commit_group;")
#define CP_WAIT0()  asm volatile("cp.async.wait_group 0;")

// ---------------------------------------------------------------------------
// Shared fp32 SIMT GEMM mainloop (proven). Epilogue varies per variant.
// ---------------------------------------------------------------------------
#define GEMM_PROLOG_AND_MAINLOOP \
    __shared__ float As[16][68];                                          \
    __shared__ float Bs[16][68];                                          \
    const int tid = threadIdx.x;                                          \
    const int tx  = tid & 15;                                             \
    const int ty  = tid >> 4;                                             \
    const int mBase = blockIdx.y * 64;                                    \
    const int nBase = blockIdx.x * 64;                                    \
    const int lr = tid >> 2;                                              \
    const int lk = (tid & 3) << 2;                                        \
    const int wr = tid >> 4;                                              \
    const int wn = (tid & 15) << 2;                                       \
    float c[4][4] = {};                                                   \
    for (int k0 = 0; k0 < 256; k0 += 16) {                                \
        float4 a = *(const float4*)&X[(mBase + lr) * 256 + k0 + lk];      \
        As[lk + 0][lr] = a.x; As[lk + 1][lr] = a.y;                       \
        As[lk + 2][lr] = a.z; As[lk + 3][lr] = a.w;                       \
        float4 bvec = *(const float4*)&W[(k0 + wr) * 256 + nBase + wn];   \
        *(float4*)&Bs[wr][wn] = bvec;                                     \
        __syncthreads();                                                  \
        _Pragma("unroll")                                                 \
        for (int k = 0; k < 16; k++) {                                    \
            float4 av = *(float4*)&As[k][ty * 4];                         \
            float4 bv = *(float4*)&Bs[k][tx * 4];                         \
            float ar[4] = {av.x, av.y, av.z, av.w};                       \
            float br[4] = {bv.x, bv.y, bv.z, bv.w};                       \
            _Pragma("unroll")                                             \
            for (int i = 0; i < 4; i++)                                   \
                _Pragma("unroll")                                         \
                for (int j = 0; j < 4; j++)                               \
                    c[i][j] += ar[i] * br[j];                             \
        }                                                                 \
        __syncthreads();                                                  \
    }

// Fused Q/K/V projections: blockIdx.z selects operand set + pack epilogue.
__global__ __launch_bounds__(256) void gemm_qkv_pack_kernel(
    const float* __restrict__ Xq, const float* __restrict__ Xk,
    const float* __restrict__ Xv,
    const float* __restrict__ Wq, const float* __restrict__ Wk,
    const float* __restrict__ Wv,
    const float* __restrict__ bq, const float* __restrict__ bk,
    const float* __restrict__ bv)
{
    const int z = blockIdx.z;
    const float* X    = (z == 0) ? Xq : (z == 1) ? Xk : Xv;
    const float* W    = (z == 0) ? Wq : (z == 1) ? Wk : Wv;
    const float* bias = (z == 0) ? bq : (z == 1) ? bk : bv;

    GEMM_PROLOG_AND_MAINLOOP

    float4 bb = *(const float4*)&bias[nBase + tx * 4];
    float bl[4] = {bb.x, bb.y, bb.z, bb.w};
    const int col0 = nBase + tx * 4;
    const int h = col0 >> 5;

    if (z < 2) {
        // Q/K: dim-pair packed hi/lo, Q pre-scaled
        const float scale = (z == 0) ? 0.17677669529663687f : 1.0f;
        float* outP = (z == 0) ? g_QP : g_KP;
        const int p0 = (col0 & 31) >> 1;
        #pragma unroll
        for (int i = 0; i < 4; i++) {
            int row = mBase + ty * 4 + i;
            int q = row >> 1, b = row & 1;
            float v0 = (c[i][0] + bl[0]) * scale;
            float v1 = (c[i][1] + bl[1]) * scale;
            float v2 = (c[i][2] + bl[2]) * scale;
            float v3 = (c[i][3] + bl[3]) * scale;
            uint32_t h0 = pk(v0, v1), h1 = pk(v2, v3);
            uint32_t e0 = pk(v0 - lowf(h0), v1 - highf(h0));
            uint32_t e1 = pk(v2 - lowf(h1), v3 - highf(h1));
            float* dst = &outP[((((b << 3) + h) << 11) + q) * 32];
            *(float2*)&dst[p0]      = make_float2(__uint_as_float(h0), __uint_as_float(h1));
            *(float2*)&dst[16 + p0] = make_float2(__uint_as_float(e0), __uint_as_float(e1));
        }
    } else {
        // V: key-pair packed hi/lo
        const int d0 = col0 & 31;
        const int L0 = (mBase + ty * 4) >> 1;
        const int kp = L0 >> 1;
        #pragma unroll
        for (int b = 0; b < 2; b++) {
            uint32_t hw[4], lw[4];
            #pragma unroll
            for (int j = 0; j < 4; j++) {
                float a = c[b][j] + bl[j];
                float d = c[2 + b][j] + bl[j];
                hw[j] = pk(a, d);
                lw[j] = pk(a - lowf(hw[j]), d - highf(hw[j]));
            }
            float* dst = &g_VP[((((b << 3) + h) << 10) + kp) * 64];
            *(float4*)&dst[d0]      = *(float4*)hw;
            *(float4*)&dst[32 + d0] = *(float4*)lw;
        }
    }
}

// Output projection: plain fp32 + bias
__global__ __launch_bounds__(256) void gemm_bias_kernel(
    const float* __restrict__ X, const float* __restrict__ W,
    const float* __restrict__ bias, float* __restrict__ out)
{
    GEMM_PROLOG_AND_MAINLOOP
    float4 bb = *(const float4*)&bias[nBase + tx * 4];
    float bl[4] = {bb.x, bb.y, bb.z, bb.w};
    #pragma unroll
    for (int i = 0; i < 4; i++) {
        float4 o;
        o.x = c[i][0] + bl[0];
        o.y = c[i][1] + bl[1];
        o.z = c[i][2] + bl[2];
        o.w = c[i][3] + bl[3];
        *(float4*)&out[(mBase + ty * 4 + i) * 256 + nBase + tx * 4] = o;
    }
}

// ---------------------------------------------------------------------------
// Flash attention, bf16 m16n8k16 3-term, split-K, cp.async DOUBLE-BUFFERED.
// CTA: 128 threads (4 warps), BQ=64, BK=64. Grid (32, 16, 2).
// Per-buffer smem: KI[64][36] (hi words 0..15, lo 16..31), VH/VL[32][40].
// ---------------------------------------------------------------------------
#define KI_PITCH 36
#define V_PITCH 40
#define KT_PER_SPLIT (L_SEQ / 64 / NSPLIT)   // 16
#define SM_KI 0
#define SM_VH (64 * KI_PITCH)
#define SM_VL (SM_VH + 32 * V_PITCH + 4)
#define BUF_FLOATS (SM_VL + 32 * V_PITCH)    // 4868 floats per buffer

__global__ __launch_bounds__(128, 4) void attn_bf16_kernel()
{
    __shared__ float SM[2 * BUF_FLOATS];

    const int tid  = threadIdx.x;
    const int warp = tid >> 5;
    const int lane = tid & 31;
    const int g    = lane >> 2;
    const int t4   = lane & 3;

    const int bh = blockIdx.y;
    const int z  = blockIdx.z;
    const int qBase = blockIdx.x * 64;
    const int q0 = warp * 16;

    // per-thread copy source/dest offsets
    const int kKey  = tid >> 1;
    const int kHalf = (tid & 1) * 16;
    const int vKp   = tid >> 2;
    const int vQtr  = tid & 3;
    const float* kSrcBase = &g_KP[(((bh << 11) + kKey) << 5) + kHalf];
    const float* vSrcBase = &g_VP[(((bh << 10) + vKp) << 6) + vQtr * 16];
    const uint32_t smBase = (uint32_t)__cvta_generic_to_shared(SM);
    const uint32_t kDst = smBase + (SM_KI + kKey * KI_PITCH + kHalf) * 4;
    const uint32_t vDst = smBase +
        (((vQtr < 2) ? SM_VH : SM_VL) + vKp * V_PITCH + (vQtr & 1) * 16) * 4;

    // ---- Q A-fragments from pre-packed gmem ----
    uint32_t qh[2][4], ql[2][4];
    {
        const int base0 = ((bh << 11) + qBase + q0 + g) * 32;
        const int base1 = base0 + 8 * 32;
        #pragma unroll
        for (int kk = 0; kk < 2; kk++) {
            int p = kk * 8 + t4;
            qh[kk][0] = __float_as_uint(g_QP[base0 + p]);
            qh[kk][1] = __float_as_uint(g_QP[base1 + p]);
            qh[kk][2] = __float_as_uint(g_QP[base0 + p + 4]);
            qh[kk][3] = __float_as_uint(g_QP[base1 + p + 4]);
            ql[kk][0] = __float_as_uint(g_QP[base0 + 16 + p]);
            ql[kk][1] = __float_as_uint(g_QP[base1 + 16 + p]);
            ql[kk][2] = __float_as_uint(g_QP[base0 + 16 + p + 4]);
            ql[kk][3] = __float_as_uint(g_QP[base1 + 16 + p + 4]);
        }
    }

    float m0 = -1e30f, m1 = -1e30f, l0 = 0.f, l1 = 0.f;
    float o[4][4];
    #pragma unroll
    for (int n = 0; n < 4; n++)
        o[n][0] = o[n][1] = o[n][2] = o[n][3] = 0.f;

    const int ktBegin = z * KT_PER_SPLIT;

    // prologue: issue copy of first tile into buffer 0
    {
        const float* ks = kSrcBase + (ktBegin * 64 << 5);
        const float* vs = vSrcBase + (ktBegin * 32 << 6);
        cpa16(kDst, ks);      cpa16(kDst + 16, ks + 4);
        cpa16(kDst + 32, ks + 8); cpa16(kDst + 48, ks + 12);
        cpa16(vDst, vs);      cpa16(vDst + 16, vs + 4);
        cpa16(vDst + 32, vs + 8); cpa16(vDst + 48, vs + 12);
        CP_COMMIT();
    }

    for (int it = 0; it < KT_PER_SPLIT; it++) {
        const int buf = it & 1;
        float* KI = SM + buf * BUF_FLOATS + SM_KI;
        float* VH = SM + buf * BUF_FLOATS + SM_VH;
        float* VL = SM + buf * BUF_FLOATS + SM_VL;

        CP_WAIT0();
        __syncthreads();

        // issue next tile's copy into the other buffer
        if (it + 1 < KT_PER_SPLIT) {
            const int kt1 = ktBegin + it + 1;
            const uint32_t off = (buf ^ 1) * BUF_FLOATS * 4;
            const float* ks = kSrcBase + (kt1 * 64 << 5);
            const float* vs = vSrcBase + (kt1 * 32 << 6);
            cpa16(kDst + off, ks);          cpa16(kDst + off + 16, ks + 4);
            cpa16(kDst + off + 32, ks + 8); cpa16(kDst + off + 48, ks + 12);
            cpa16(vDst + off, vs);          cpa16(vDst + off + 16, vs + 4);
            cpa16(vDst + off + 32, vs + 8); cpa16(vDst + off + 48, vs + 12);
            CP_COMMIT();
        }

        // ---- S = Q K^T (3x bf16 k16) ----
        float s[8][4];
        #pragma unroll
        for (int j = 0; j < 8; j++)
            s[j][0] = s[j][1] = s[j][2] = s[j][3] = 0.f;
        #pragma unroll
        for (int kk = 0; kk < 2; kk++) {
            #pragma unroll
            for (int j = 0; j < 8; j++) {
                int base = (j * 8 + g) * KI_PITCH + kk * 8;
                uint32_t kb0h = __float_as_uint(KI[base + t4]);
                uint32_t kb1h = __float_as_uint(KI[base + 4 + t4]);
                uint32_t kb0l = __float_as_uint(KI[base + 16 + t4]);
                uint32_t kb1l = __float_as_uint(KI[base + 20 + t4]);
                mma16(s[j], qh[kk], kb0h, kb1h);
                mma16(s[j], ql[kk], kb0h, kb1h);
                mma16(s[j], qh[kk], kb0l, kb1l);
            }
        }

        // ---- online softmax ----
        float mx0 = -1e30f, mx1 = -1e30f;
        #pragma unroll
        for (int j = 0; j < 8; j++) {
            mx0 = fmaxf(mx0, fmaxf(s[j][0], s[j][1]));
            mx1 = fmaxf(mx1, fmaxf(s[j][2], s[j][3]));
        }
        mx0 = fmaxf(mx0, __shfl_xor_sync(0xffffffffu, mx0, 1));
        mx0 = fmaxf(mx0, __shfl_xor_sync(0xffffffffu, mx0, 2));
        mx1 = fmaxf(mx1, __shfl_xor_sync(0xffffffffu, mx1, 1));
        mx1 = fmaxf(mx1, __shfl_xor_sync(0xffffffffu, mx1, 2));
        float mn0 = fmaxf(m0, mx0), mn1 = fmaxf(m1, mx1);
        float al0 = __expf(m0 - mn0), al1 = __expf(m1 - mn1);
        float sum0 = 0.f, sum1 = 0.f;
        #pragma unroll
        for (int j = 0; j < 8; j++) {
            s[j][0] = __expf(s[j][0] - mn0);
            s[j][1] = __expf(s[j][1] - mn0);
            sum0 += s[j][0] + s[j][1];
            s[j][2] = __expf(s[j][2] - mn1);
            s[j][3] = __expf(s[j][3] - mn1);
            sum1 += s[j][2] + s[j][3];
        }
        sum0 += __shfl_xor_sync(0xffffffffu, sum0, 1);
        sum0 += __shfl_xor_sync(0xffffffffu, sum0, 2);
        sum1 += __shfl_xor_sync(0xffffffffu, sum1, 1);
        sum1 += __shfl_xor_sync(0xffffffffu, sum1, 2);
        l0 = l0 * al0 + sum0; m0 = mn0;
        l1 = l1 * al1 + sum1; m1 = mn1;
        #pragma unroll
        for (int n = 0; n < 4; n++) {
            o[n][0] *= al0; o[n][1] *= al0;
            o[n][2] *= al1; o[n][3] *= al1;
        }

        // ---- O += P V ----
        #pragma unroll
        for (int kb = 0; kb < 4; kb++) {
            uint32_t pa[4], pl[4];
            {
                float x0 = s[2 * kb][0],     x1 = s[2 * kb][1];
                float y0 = s[2 * kb][2],     y1 = s[2 * kb][3];
                float z0 = s[2 * kb + 1][0], z1 = s[2 * kb + 1][1];
                float w0 = s[2 * kb + 1][2], w1 = s[2 * kb + 1][3];
                pa[0] = pk(x0, x1); pl[0] = pk(x0 - lowf(pa[0]), x1 - highf(pa[0]));
                pa[1] = pk(y0, y1); pl[1] = pk(y0 - lowf(pa[1]), y1 - highf(pa[1]));
                pa[2] = pk(z0, z1); pl[2] = pk(z0 - lowf(pa[2]), z1 - highf(pa[2]));
                pa[3] = pk(w0, w1); pl[3] = pk(w0 - lowf(pa[3]), w1 - highf(pa[3]));
            }
            int r0 = (kb * 8 + t4) * V_PITCH;
            int r1 = (kb * 8 + 4 + t4) * V_PITCH;
            #pragma unroll
            for (int n = 0; n < 4; n++) {
                int dc = n * 8 + g;
                uint32_t vb0h = __float_as_uint(VH[r0 + dc]);
                uint32_t vb1h = __float_as_uint(VH[r1 + dc]);
                uint32_t vb0l = __float_as_uint(VL[r0 + dc]);
                uint32_t vb1l = __float_as_uint(VL[r1 + dc]);
                mma16(o[n], pa, vb0h, vb1h);
                mma16(o[n], pl, vb0h, vb1h);
                mma16(o[n], pa, vb0l, vb1l);
            }
        }
        __syncthreads();   // all warps done with this buffer before its reuse
    }

    // ---- epilogue: write unnormalized partials ----
    const int pbase = (z * NH * B_SZ + bh) * L_SEQ;
    int qr0 = qBase + q0 + g;
    int qr1 = qr0 + 8;
    #pragma unroll
    for (int n = 0; n < 4; n++) {
        int col = n * 8 + 2 * t4;
        *(float2*)&g_Po[(pbase + qr0) * HD + col] = make_float2(o[n][0], o[n][1]);
        *(float2*)&g_Po[(pbase + qr1) * HD + col] = make_float2(o[n][2], o[n][3]);
    }
    if (t4 == 0) {
        g_Pm[pbase + qr0] = m0;  g_Pl[pbase + qr0] = l0;
        g_Pm[pbase + qr1] = m1;  g_Pl[pbase + qr1] = l1;
    }
}

// ---------------------------------------------------------------------------
// Merge the NSPLIT partials (exact log-sum-exp), write g_O.
// ---------------------------------------------------------------------------
__global__ __launch_bounds__(256) void attn_merge_kernel()
{
    const int tid = threadIdx.x;
    const int row = blockIdx.x * 32 + (tid >> 3);
    const int d   = (tid & 7) * 4;

    const int bh = row >> 11;
    const int q  = row & 2047;
    const int b  = bh >> 3;
    const int h  = bh & 7;

    float m0 = g_Pm[row], l0 = g_Pl[row];
    float m1 = g_Pm[BHL + row], l1 = g_Pl[BHL + row];
    float ms = fmaxf(m0, m1);
    float w0 = __expf(m0 - ms), w1 = __expf(m1 - ms);
    float inv = 1.0f / (l0 * w0 + l1 * w1);
    w0 *= inv; w1 *= inv;

    float4 p0 = *(const float4*)&g_Po[row * HD + d];
    float4 p1 = *(const float4*)&g_Po[(BHL + row) * HD + d];
    float4 r;
    r.x = p0.x * w0 + p1.x * w1;
    r.y = p0.y * w0 + p1.y * w1;
    r.z = p0.z * w0 + p1.z * w1;
    r.w = p0.w * w0 + p1.w * w1;
    *(float4*)&g_O[(q * B_SZ + b) * E_DIM + h * HD + d] = r;
}

// ---------------------------------------------------------------------------
extern "C" void kernel_launch(void* const* d_in, const int* in_sizes, int n_in,
                              void* d_out, int out_size)
{
    const float* query = (const float*)d_in[0];
    const float* key_  = (const float*)d_in[1];
    const float* value = (const float*)d_in[2];
    const float* Wq = (const float*)d_in[3];
    const float* bq = (const float*)d_in[4];
    const float* Wk = (const float*)d_in[5];
    const float* bk = (const float*)d_in[6];
    const float* Wv = (const float*)d_in[7];
    const float* bv = (const float*)d_in[8];
    const float* Wp = (const float*)d_in[9];
    const float* bp = (const float*)d_in[10];
    float* out = (float*)d_out;

    float* obuf;
    cudaGetSymbolAddress((void**)&obuf, g_O);

    dim3 gq(E_DIM / 64, M_ROWS / 64, 3);   // fused QKV: (4, 64, 3)
    gemm_qkv_pack_kernel<<<gq, 256>>>(query, key_, value,
                                      Wq, Wk, Wv, bq, bk, bv);
    attn_bf16_kernel<<<dim3(L_SEQ / 64, B_SZ * NH, NSPLIT), 128>>>();
    attn_merge_kernel<<<BHL / 32, 256>>>();
    gemm_bias_kernel<<<dim3(E_DIM / 64, M_ROWS / 64), 256>>>(obuf, Wp, bp, out);
}

// round 11
// speedup vs baseline: 1.4907x; 1.0809x over previous
#include <cuda_runtime.h>
#include <math.h>
#include <stdint.h>

#define L_SEQ 2048
#define B_SZ 2
#define E_DIM 256
#define NH 8
#define HD 32
#define M_ROWS (L_SEQ * B_SZ)   // 4096
#define NSPLIT 2
#define BHL (NH * B_SZ * L_SEQ) // 32768

// ---- packed global scratch (allocation-free rule) ----
// XP*/OP: [m][256 words]: word p = bf16x2(x[2p],x[2p+1]) hi, word 128+p = lo
// WP*:    [n][256 words]: word p = bf16x2(W[2p][n],W[2p+1][n]) hi, 128+p = lo
// QP/KP:  [bh][row][32]: word p = dim-pair hi, 16+p = lo  (Q pre-scaled)
// VP:     [bh][kp][64]: word d = bf16x2(V[2kp][d],V[2kp+1][d]) hi, 32+d = lo
static __device__ float g_XPq[M_ROWS * 256];
static __device__ float g_XPk[M_ROWS * 256];
static __device__ float g_XPv[M_ROWS * 256];
static __device__ float g_WPq[256 * 256];
static __device__ float g_WPk[256 * 256];
static __device__ float g_WPv[256 * 256];
static __device__ float g_WPp[256 * 256];
static __device__ float g_QP[16 * 2048 * 32];
static __device__ float g_KP[16 * 2048 * 32];
static __device__ float g_VP[16 * 1024 * 64];
static __device__ float g_OP[M_ROWS * 256];
static __device__ float g_Po[NSPLIT * BHL * HD];
static __device__ float g_Pm[NSPLIT * BHL];
static __device__ float g_Pl[NSPLIT * BHL];

// ---------------------------------------------------------------------------
// helpers
// ---------------------------------------------------------------------------
__device__ __forceinline__ uint32_t pk(float lo_e, float hi_e) {
    return (__float_as_uint(hi_e) & 0xFFFF0000u) | (__float_as_uint(lo_e) >> 16);
}
__device__ __forceinline__ float lowf(uint32_t w)  { return __uint_as_float(w << 16); }
__device__ __forceinline__ float highf(uint32_t w) { return __uint_as_float(w & 0xFFFF0000u); }

__device__ __forceinline__ void mma16(float c[4], const uint32_t a[4],
                                      uint32_t b0, uint32_t b1) {
    asm("mma.sync.aligned.m16n8k16.row.col.f32.bf16.bf16.f32 "
        "{%0,%1,%2,%3}, {%4,%5,%6,%7}, {%8,%9}, {%0,%1,%2,%3};"
        : "+f"(c[0]), "+f"(c[1]), "+f"(c[2]), "+f"(c[3])
        : "r"(a[0]), "r"(a[1]), "r"(a[2]), "r"(a[3]), "r"(b0), "r"(b1));
}

__device__ __forceinline__ void cpa16(uint32_t dst_smem, const float* src) {
    asm volatile("cp.async.cg.shared.global [%0], [%1], 16;"
                 :: "r"(dst_smem), "l"(src));
}
#define CP_COMMIT() asm volatile("cp.async.commit_group;")
#define CP_WAIT0()  asm volatile("cp.async.wait_group 0;")

// ---------------------------------------------------------------------------
// pack X inputs: fp32 [m][256] -> dim-pair hi/lo packed [m][256 words]
// grid (128, 3), 256 threads. Thread: one (row, 32-dim segment).
// ---------------------------------------------------------------------------
__global__ __launch_bounds__(256) void pack_x_kernel(
    const float* __restrict__ q, const float* __restrict__ k,
    const float* __restrict__ v)
{
    const int z = blockIdx.y;
    const float* src = (z == 0) ? q : (z == 1) ? k : v;
    float* dst = (z == 0) ? g_XPq : (z == 1) ? g_XPk : g_XPv;
    int idx = blockIdx.x * 256 + threadIdx.x;   // 0..32767
    int row = idx >> 3, seg = idx & 7;
    const float* s = src + row * 256 + seg * 32;
    float* dh = dst + row * 256 + seg * 16;
    float* dl = dh + 128;
    #pragma unroll
    for (int j = 0; j < 4; j++) {
        float4 a  = *(const float4*)(s + j * 8);
        float4 b2 = *(const float4*)(s + j * 8 + 4);
        uint32_t h0 = pk(a.x, a.y),  h1 = pk(a.z, a.w);
        uint32_t h2 = pk(b2.x, b2.y), h3 = pk(b2.z, b2.w);
        uint32_t l0 = pk(a.x - lowf(h0), a.y - highf(h0));
        uint32_t l1 = pk(a.z - lowf(h1), a.w - highf(h1));
        uint32_t l2 = pk(b2.x - lowf(h2), b2.y - highf(h2));
        uint32_t l3 = pk(b2.z - lowf(h3), b2.w - highf(h3));
        *(float4*)(dh + j * 4) = make_float4(__uint_as_float(h0), __uint_as_float(h1),
                                             __uint_as_float(h2), __uint_as_float(h3));
        *(float4*)(dl + j * 4) = make_float4(__uint_as_float(l0), __uint_as_float(l1),
                                             __uint_as_float(l2), __uint_as_float(l3));
    }
}

// ---------------------------------------------------------------------------
// pack W: fp32 [k][n] -> k-pair hi/lo packed per n row. grid (8,4), 256 thr.
// ---------------------------------------------------------------------------
__global__ __launch_bounds__(256) void pack_w_kernel(
    const float* __restrict__ Wq, const float* __restrict__ Wk,
    const float* __restrict__ Wv, const float* __restrict__ Wp)
{
    const int z = blockIdx.y;
    const float* W = (z == 0) ? Wq : (z == 1) ? Wk : (z == 2) ? Wv : Wp;
    float* WP = (z == 0) ? g_WPq : (z == 1) ? g_WPk : (z == 2) ? g_WPv : g_WPp;
    const int n = threadIdx.x;
    const int p0 = blockIdx.x * 16;
    #pragma unroll
    for (int i = 0; i < 16; i++) {
        int p = p0 + i;
        float a  = W[(2 * p) * 256 + n];
        float b2 = W[(2 * p + 1) * 256 + n];
        uint32_t hw = pk(a, b2);
        uint32_t lw = pk(a - lowf(hw), b2 - highf(hw));
        WP[n * 256 + p]       = __uint_as_float(hw);
        WP[n * 256 + 128 + p] = __uint_as_float(lw);
    }
}

// ---------------------------------------------------------------------------
// bf16 3-term GEMM mainloop (tile 64x64, K-chunks of 32, cp.async dbl-buf).
// 128 threads, warp = 16 rows x 64 cols (8 m16n8 tiles). Pitch 36 (CF banks).
// Leaves accumulators in c[8][4]; smem SM2 reusable after __syncthreads().
// ---------------------------------------------------------------------------
#define BF16_GEMM_MAINLOOP(XPTR, WPTR)                                        \
    __shared__ float SM2[2 * 4608];                                           \
    const int tid = threadIdx.x, lane = tid & 31;                             \
    const int warp = tid >> 5, g = lane >> 2, t4 = lane & 3;                  \
    const int mBase = blockIdx.y * 64, nBase = blockIdx.x * 64;               \
    const int m0 = warp * 16;                                                 \
    const int crow = tid >> 1, chalf = tid & 1;                               \
    const float* srcA = (XPTR) + (mBase + crow) * 256 + chalf * 128;          \
    const float* srcB = (WPTR) + (nBase + crow) * 256 + chalf * 128;          \
    const uint32_t smb = (uint32_t)__cvta_generic_to_shared(SM2);             \
    const uint32_t dAa = smb + (crow * 36 + chalf * 16) * 4;                  \
    const uint32_t dBb = smb + (2304 + crow * 36 + chalf * 16) * 4;           \
    float c[8][4] = {};                                                       \
    {                                                                         \
        cpa16(dAa, srcA);          cpa16(dAa + 16, srcA + 4);                 \
        cpa16(dAa + 32, srcA + 8); cpa16(dAa + 48, srcA + 12);                \
        cpa16(dBb, srcB);          cpa16(dBb + 16, srcB + 4);                 \
        cpa16(dBb + 32, srcB + 8); cpa16(dBb + 48, srcB + 12);                \
        CP_COMMIT();                                                          \
    }                                                                         \
    for (int ch = 0; ch < 8; ch++) {                                          \
        const int buf = ch & 1;                                               \
        float* SA = SM2 + buf * 4608;                                         \
        float* SB = SA + 2304;                                                \
        CP_WAIT0(); __syncthreads();                                          \
        if (ch < 7) {                                                         \
            const uint32_t off = (uint32_t)(buf ^ 1) * 4608 * 4;              \
            const float* sa = srcA + (ch + 1) * 16;                           \
            const float* sb = srcB + (ch + 1) * 16;                           \
            cpa16(dAa + off, sa);          cpa16(dAa + off + 16, sa + 4);     \
            cpa16(dAa + off + 32, sa + 8); cpa16(dAa + off + 48, sa + 12);    \
            cpa16(dBb + off, sb);          cpa16(dBb + off + 16, sb + 4);     \
            cpa16(dBb + off + 32, sb + 8); cpa16(dBb + off + 48, sb + 12);    \
            CP_COMMIT();                                                      \
        }                                                                     \
        _Pragma("unroll")                                                     \
        for (int kk = 0; kk < 2; kk++) {                                      \
            int aw = kk * 8 + t4;                                             \
            int ra = (m0 + g) * 36, rb = (m0 + g + 8) * 36;                   \
            uint32_t ah[4], al[4];                                            \
            ah[0] = __float_as_uint(SA[ra + aw]);                             \
            ah[1] = __float_as_uint(SA[rb + aw]);                             \
            ah[2] = __float_as_uint(SA[ra + aw + 4]);                         \
            ah[3] = __float_as_uint(SA[rb + aw + 4]);                         \
            al[0] = __float_as_uint(SA[ra + 16 + aw]);                        \
            al[1] = __float_as_uint(SA[rb + 16 + aw]);                        \
            al[2] = __float_as_uint(SA[ra + 16 + aw + 4]);                    \
            al[3] = __float_as_uint(SA[rb + 16 + aw + 4]);                    \
            _Pragma("unroll")                                                 \
            for (int nt = 0; nt < 8; nt++) {                                  \
                int bb = (nt * 8 + g) * 36 + kk * 8 + t4;                     \
                uint32_t bh0 = __float_as_uint(SB[bb]);                       \
                uint32_t bh1 = __float_as_uint(SB[bb + 4]);                   \
                uint32_t bl0 = __float_as_uint(SB[bb + 16]);                  \
                uint32_t bl1 = __float_as_uint(SB[bb + 20]);                  \
                mma16(c[nt], ah, bh0, bh1);                                   \
                mma16(c[nt], al, bh0, bh1);                                   \
                mma16(c[nt], ah, bl0, bl1);                                   \
            }                                                                 \
        }                                                                     \
    }

// Fused QKV projections (bf16 tensor): z selects operand set + epilogue.
__global__ __launch_bounds__(128) void gemm_qkv_bf16(
    const float* __restrict__ bq, const float* __restrict__ bk,
    const float* __restrict__ bv)
{
    const int z = blockIdx.z;
    const float* XPTR = (z == 0) ? g_XPq : (z == 1) ? g_XPk : g_XPv;
    const float* WPTR = (z == 0) ? g_WPq : (z == 1) ? g_WPk : g_WPv;
    const float* bias = (z == 0) ? bq : (z == 1) ? bk : bv;

    BF16_GEMM_MAINLOOP(XPTR, WPTR)

    if (z < 2) {
        // Q/K epilogue: dim-pair packed hi/lo (Q pre-scaled)
        const float scale = (z == 0) ? 0.17677669529663687f : 1.0f;
        float* outP = (z == 0) ? g_QP : g_KP;
        #pragma unroll
        for (int nt = 0; nt < 8; nt++) {
            int col = nBase + nt * 8 + 2 * t4;
            float b0 = bias[col], b1 = bias[col + 1];
            int h = col >> 5, p0 = (col & 31) >> 1;
            int m1 = mBase + m0 + g;
            {
                float v0 = (c[nt][0] + b0) * scale;
                float v1 = (c[nt][1] + b1) * scale;
                uint32_t hw = pk(v0, v1);
                uint32_t lw = pk(v0 - lowf(hw), v1 - highf(hw));
                float* dst = &outP[(((((m1 & 1) << 3) + h) << 11) + (m1 >> 1)) * 32];
                dst[p0]      = __uint_as_float(hw);
                dst[16 + p0] = __uint_as_float(lw);
            }
            int m2 = m1 + 8;
            {
                float v0 = (c[nt][2] + b0) * scale;
                float v1 = (c[nt][3] + b1) * scale;
                uint32_t hw = pk(v0, v1);
                uint32_t lw = pk(v0 - lowf(hw), v1 - highf(hw));
                float* dst = &outP[(((((m2 & 1) << 3) + h) << 11) + (m2 >> 1)) * 32];
                dst[p0]      = __uint_as_float(hw);
                dst[16 + p0] = __uint_as_float(lw);
            }
        }
    } else {
        // V epilogue: stage fp32 in smem, repack as key-pairs
        __syncthreads();
        float* ST = SM2;   // 64 x 68
        #pragma unroll
        for (int nt = 0; nt < 8; nt++) {
            int cl = nt * 8 + 2 * t4;
            float b0 = bias[nBase + cl], b1 = bias[nBase + cl + 1];
            ST[(m0 + g) * 68 + cl]         = c[nt][0] + b0;
            ST[(m0 + g) * 68 + cl + 1]     = c[nt][1] + b1;
            ST[(m0 + g + 8) * 68 + cl]     = c[nt][2] + b0;
            ST[(m0 + g + 8) * 68 + cl + 1] = c[nt][3] + b1;
        }
        __syncthreads();
        int kp_l = tid >> 3;          // 0..15
        int bb2  = (tid >> 2) & 1;    // batch
        int dseg = (tid & 3) * 16;    // col segment
        int r0 = 4 * kp_l + bb2, r1 = r0 + 2;
        int hh = (nBase + dseg) >> 5;
        int d0 = (nBase + dseg) & 31;
        float* dst = &g_VP[((((bb2 << 3) + hh) << 10) + (mBase >> 2) + kp_l) * 64];
        #pragma unroll
        for (int i = 0; i < 16; i++) {
            float a  = ST[r0 * 68 + dseg + i];
            float b3 = ST[r1 * 68 + dseg + i];
            uint32_t hw = pk(a, b3);
            uint32_t lw = pk(a - lowf(hw), b3 - highf(hw));
            dst[d0 + i]      = __uint_as_float(hw);
            dst[32 + d0 + i] = __uint_as_float(lw);
        }
    }
}

// Output projection (bf16 tensor): A = packed OP, epilogue fp32 + bias.
__global__ __launch_bounds__(128) void gemm_out_bf16(
    const float* __restrict__ bp, float* __restrict__ out)
{
    BF16_GEMM_MAINLOOP(g_OP, g_WPp)
    #pragma unroll
    for (int nt = 0; nt < 8; nt++) {
        int col = nBase + nt * 8 + 2 * t4;
        float b0 = bp[col], b1 = bp[col + 1];
        int m1 = mBase + m0 + g;
        *(float2*)&out[m1 * 256 + col] =
            make_float2(c[nt][0] + b0, c[nt][1] + b1);
        *(float2*)&out[(m1 + 8) * 256 + col] =
            make_float2(c[nt][2] + b0, c[nt][3] + b1);
    }
}

// ---------------------------------------------------------------------------
// Flash attention, bf16 m16n8k16 3-term, split-K, cp.async double-buffered.
// (unchanged from round 10)
// ---------------------------------------------------------------------------
#define KI_PITCH 36
#define V_PITCH 40
#define KT_PER_SPLIT (L_SEQ / 64 / NSPLIT)   // 16
#define SM_KI 0
#define SM_VH (64 * KI_PITCH)
#define SM_VL (SM_VH + 32 * V_PITCH + 4)
#define BUF_FLOATS (SM_VL + 32 * V_PITCH)

__global__ __launch_bounds__(128, 4) void attn_bf16_kernel()
{
    __shared__ float SM[2 * BUF_FLOATS];

    const int tid  = threadIdx.x;
    const int warp = tid >> 5;
    const int lane = tid & 31;
    const int g    = lane >> 2;
    const int t4   = lane & 3;

    const int bh = blockIdx.y;
    const int z  = blockIdx.z;
    const int qBase = blockIdx.x * 64;
    const int q0 = warp * 16;

    const int kKey  = tid >> 1;
    const int kHalf = (tid & 1) * 16;
    const int vKp   = tid >> 2;
    const int vQtr  = tid & 3;
    const float* kSrcBase = &g_KP[(((bh << 11) + kKey) << 5) + kHalf];
    const float* vSrcBase = &g_VP[(((bh << 10) + vKp) << 6) + vQtr * 16];
    const uint32_t smBase = (uint32_t)__cvta_generic_to_shared(SM);
    const uint32_t kDst = smBase + (SM_KI + kKey * KI_PITCH + kHalf) * 4;
    const uint32_t vDst = smBase +
        (((vQtr < 2) ? SM_VH : SM_VL) + vKp * V_PITCH + (vQtr & 1) * 16) * 4;

    uint32_t qh[2][4], ql[2][4];
    {
        const int base0 = ((bh << 11) + qBase + q0 + g) * 32;
        const int base1 = base0 + 8 * 32;
        #pragma unroll
        for (int kk = 0; kk < 2; kk++) {
            int p = kk * 8 + t4;
            qh[kk][0] = __float_as_uint(g_QP[base0 + p]);
            qh[kk][1] = __float_as_uint(g_QP[base1 + p]);
            qh[kk][2] = __float_as_uint(g_QP[base0 + p + 4]);
            qh[kk][3] = __float_as_uint(g_QP[base1 + p + 4]);
            ql[kk][0] = __float_as_uint(g_QP[base0 + 16 + p]);
            ql[kk][1] = __float_as_uint(g_QP[base1 + 16 + p]);
            ql[kk][2] = __float_as_uint(g_QP[base0 + 16 + p + 4]);
            ql[kk][3] = __float_as_uint(g_QP[base1 + 16 + p + 4]);
        }
    }

    float m0 = -1e30f, m1 = -1e30f, l0 = 0.f, l1 = 0.f;
    float o[4][4];
    #pragma unroll
    for (int n = 0; n < 4; n++)
        o[n][0] = o[n][1] = o[n][2] = o[n][3] = 0.f;

    const int ktBegin = z * KT_PER_SPLIT;

    {
        const float* ks = kSrcBase + (ktBegin * 64 << 5);
        const float* vs = vSrcBase + (ktBegin * 32 << 6);
        cpa16(kDst, ks);          cpa16(kDst + 16, ks + 4);
        cpa16(kDst + 32, ks + 8); cpa16(kDst + 48, ks + 12);
        cpa16(vDst, vs);          cpa16(vDst + 16, vs + 4);
        cpa16(vDst + 32, vs + 8); cpa16(vDst + 48, vs + 12);
        CP_COMMIT();
    }

    for (int it = 0; it < KT_PER_SPLIT; it++) {
        const int buf = it & 1;
        float* KI = SM + buf * BUF_FLOATS + SM_KI;
        float* VH = SM + buf * BUF_FLOATS + SM_VH;
        float* VL = SM + buf * BUF_FLOATS + SM_VL;

        CP_WAIT0();
        __syncthreads();

        if (it + 1 < KT_PER_SPLIT) {
            const int kt1 = ktBegin + it + 1;
            const uint32_t off = (uint32_t)(buf ^ 1) * BUF_FLOATS * 4;
            const float* ks = kSrcBase + (kt1 * 64 << 5);
            const float* vs = vSrcBase + (kt1 * 32 << 6);
            cpa16(kDst + off, ks);          cpa16(kDst + off + 16, ks + 4);
            cpa16(kDst + off + 32, ks + 8); cpa16(kDst + off + 48, ks + 12);
            cpa16(vDst + off, vs);          cpa16(vDst + off + 16, vs + 4);
            cpa16(vDst + off + 32, vs + 8); cpa16(vDst + off + 48, vs + 12);
            CP_COMMIT();
        }

        float s[8][4];
        #pragma unroll
        for (int j = 0; j < 8; j++)
            s[j][0] = s[j][1] = s[j][2] = s[j][3] = 0.f;
        #pragma unroll
        for (int kk = 0; kk < 2; kk++) {
            #pragma unroll
            for (int j = 0; j < 8; j++) {
                int base = (j * 8 + g) * KI_PITCH + kk * 8;
                uint32_t kb0h = __float_as_uint(KI[base + t4]);
                uint32_t kb1h = __float_as_uint(KI[base + 4 + t4]);
                uint32_t kb0l = __float_as_uint(KI[base + 16 + t4]);
                uint32_t kb1l = __float_as_uint(KI[base + 20 + t4]);
                mma16(s[j], qh[kk], kb0h, kb1h);
                mma16(s[j], ql[kk], kb0h, kb1h);
                mma16(s[j], qh[kk], kb0l, kb1l);
            }
        }

        float mx0 = -1e30f, mx1 = -1e30f;
        #pragma unroll
        for (int j = 0; j < 8; j++) {
            mx0 = fmaxf(mx0, fmaxf(s[j][0], s[j][1]));
            mx1 = fmaxf(mx1, fmaxf(s[j][2], s[j][3]));
        }
        mx0 = fmaxf(mx0, __shfl_xor_sync(0xffffffffu, mx0, 1));
        mx0 = fmaxf(mx0, __shfl_xor_sync(0xffffffffu, mx0, 2));
        mx1 = fmaxf(mx1, __shfl_xor_sync(0xffffffffu, mx1, 1));
        mx1 = fmaxf(mx1, __shfl_xor_sync(0xffffffffu, mx1, 2));
        float mn0 = fmaxf(m0, mx0), mn1 = fmaxf(m1, mx1);
        float al0 = __expf(m0 - mn0), al1 = __expf(m1 - mn1);
        float sum0 = 0.f, sum1 = 0.f;
        #pragma unroll
        for (int j = 0; j < 8; j++) {
            s[j][0] = __expf(s[j][0] - mn0);
            s[j][1] = __expf(s[j][1] - mn0);
            sum0 += s[j][0] + s[j][1];
            s[j][2] = __expf(s[j][2] - mn1);
            s[j][3] = __expf(s[j][3] - mn1);
            sum1 += s[j][2] + s[j][3];
        }
        sum0 += __shfl_xor_sync(0xffffffffu, sum0, 1);
        sum0 += __shfl_xor_sync(0xffffffffu, sum0, 2);
        sum1 += __shfl_xor_sync(0xffffffffu, sum1, 1);
        sum1 += __shfl_xor_sync(0xffffffffu, sum1, 2);
        l0 = l0 * al0 + sum0; m0 = mn0;
        l1 = l1 * al1 + sum1; m1 = mn1;
        #pragma unroll
        for (int n = 0; n < 4; n++) {
            o[n][0] *= al0; o[n][1] *= al0;
            o[n][2] *= al1; o[n][3] *= al1;
        }

        #pragma unroll
        for (int kb = 0; kb < 4; kb++) {
            uint32_t pa[4], pl[4];
            {
                float x0 = s[2 * kb][0],     x1 = s[2 * kb][1];
                float y0 = s[2 * kb][2],     y1 = s[2 * kb][3];
                float z0 = s[2 * kb + 1][0], z1 = s[2 * kb + 1][1];
                float w0 = s[2 * kb + 1][2], w1 = s[2 * kb + 1][3];
                pa[0] = pk(x0, x1); pl[0] = pk(x0 - lowf(pa[0]), x1 - highf(pa[0]));
                pa[1] = pk(y0, y1); pl[1] = pk(y0 - lowf(pa[1]), y1 - highf(pa[1]));
                pa[2] = pk(z0, z1); pl[2] = pk(z0 - lowf(pa[2]), z1 - highf(pa[2]));
                pa[3] = pk(w0, w1); pl[3] = pk(w0 - lowf(pa[3]), w1 - highf(pa[3]));
            }
            int r0 = (kb * 8 + t4) * V_PITCH;
            int r1 = (kb * 8 + 4 + t4) * V_PITCH;
            #pragma unroll
            for (int n = 0; n < 4; n++) {
                int dc = n * 8 + g;
                uint32_t vb0h = __float_as_uint(VH[r0 + dc]);
                uint32_t vb1h = __float_as_uint(VH[r1 + dc]);
                uint32_t vb0l = __float_as_uint(VL[r0 + dc]);
                uint32_t vb1l = __float_as_uint(VL[r1 + dc]);
                mma16(o[n], pa, vb0h, vb1h);
                mma16(o[n], pl, vb0h, vb1h);
                mma16(o[n], pa, vb0l, vb1l);
            }
        }
        __syncthreads();
    }

    const int pbase = (z * NH * B_SZ + bh) * L_SEQ;
    int qr0 = qBase + q0 + g;
    int qr1 = qr0 + 8;
    #pragma unroll
    for (int n = 0; n < 4; n++) {
        int col = n * 8 + 2 * t4;
        *(float2*)&g_Po[(pbase + qr0) * HD + col] = make_float2(o[n][0], o[n][1]);
        *(float2*)&g_Po[(pbase + qr1) * HD + col] = make_float2(o[n][2], o[n][3]);
    }
    if (t4 == 0) {
        g_Pm[pbase + qr0] = m0;  g_Pl[pbase + qr0] = l0;
        g_Pm[pbase + qr1] = m1;  g_Pl[pbase + qr1] = l1;
    }
}

// ---------------------------------------------------------------------------
// Merge partials (exact log-sum-exp); writes PACKED OP for out projection.
// ---------------------------------------------------------------------------
__global__ __launch_bounds__(256) void attn_merge_kernel()
{
    const int tid = threadIdx.x;
    const int row = blockIdx.x * 32 + (tid >> 3);
    const int d   = (tid & 7) * 4;

    const int bh = row >> 11;
    const int q  = row & 2047;
    const int b  = bh >> 3;
    const int h  = bh & 7;

    float m0 = g_Pm[row], l0 = g_Pl[row];
    float m1 = g_Pm[BHL + row], l1 = g_Pl[BHL + row];
    float ms = fmaxf(m0, m1);
    float w0 = __expf(m0 - ms), w1 = __expf(m1 - ms);
    float inv = 1.0f / (l0 * w0 + l1 * w1);
    w0 *= inv; w1 *= inv;

    float4 p0 = *(const float4*)&g_Po[row * HD + d];
    float4 p1 = *(const float4*)&g_Po[(BHL + row) * HD + d];
    float r0 = p0.x * w0 + p1.x * w1;
    float r1 = p0.y * w0 + p1.y * w1;
    float r2 = p0.z * w0 + p1.z * w1;
    float r3 = p0.w * w0 + p1.w * w1;

    uint32_t h0 = pk(r0, r1), h1 = pk(r2, r3);
    uint32_t e0 = pk(r0 - lowf(h0), r1 - highf(h0));
    uint32_t e1 = pk(r2 - lowf(h1), r3 - highf(h1));
    int m = q * B_SZ + b;
    int p = h * 16 + (d >> 1);
    *(float2*)&g_OP[m * 256 + p] =
        make_float2(__uint_as_float(h0), __uint_as_float(h1));
    *(float2*)&g_OP[m * 256 + 128 + p] =
        make_float2(__uint_as_float(e0), __uint_as_float(e1));
}

// ---------------------------------------------------------------------------
extern "C" void kernel_launch(void* const* d_in, const int* in_sizes, int n_in,
                              void* d_out, int out_size)
{
    const float* query = (const float*)d_in[0];
    const float* key_  = (const float*)d_in[1];
    const float* value = (const float*)d_in[2];
    const float* Wq = (const float*)d_in[3];
    const float* bq = (const float*)d_in[4];
    const float* Wk = (const float*)d_in[5];
    const float* bk = (const float*)d_in[6];
    const float* Wv = (const float*)d_in[7];
    const float* bv = (const float*)d_in[8];
    const float* Wp = (const float*)d_in[9];
    const float* bp = (const float*)d_in[10];
    float* out = (float*)d_out;

    pack_x_kernel<<<dim3(128, 3), 256>>>(query, key_, value);
    pack_w_kernel<<<dim3(8, 4), 256>>>(Wq, Wk, Wv, Wp);
    gemm_qkv_bf16<<<dim3(4, 64, 3), 128>>>(bq, bk, bv);
    attn_bf16_kernel<<<dim3(L_SEQ / 64, B_SZ * NH, NSPLIT), 128>>>();
    attn_merge_kernel<<<BHL / 32, 256>>>();
    gemm_out_bf16<<<dim3(4, 64), 128>>>(bp, out);
}